// round 13
// baseline (speedup 1.0000x reference)
#include <cuda_runtime.h>
#include <cstdint>

#define B_SZ   2
#define SEQ    2048
#define DM     2048
#define NH     32
#define NKV    8
#define HD     64
#define NT     (B_SZ * SEQ)   // 4096 tokens

// ---------------- scratch (static device globals; no runtime allocation) ----
__device__ float g_q[(size_t)NT * DM];          // 32 MB
__device__ float g_k[(size_t)NT * NKV * HD];    //  8 MB
__device__ float g_v[(size_t)NT * NKV * HD];    //  8 MB
__device__ float g_o[(size_t)NT * DM];          // 32 MB (attention writes tf32-rounded)
__device__ float g_xt[(size_t)NT * DM];         // 32 MB
__device__ float g_wq[(size_t)DM * DM];         // 16 MB
__device__ float g_wk[(size_t)(NKV * HD) * DM]; //  4 MB
__device__ float g_wv[(size_t)(NKV * HD) * DM]; //  4 MB
__device__ float g_wo[(size_t)DM * DM];         // 16 MB

__device__ __forceinline__ float to_tf32(float x) {
    asm("cvt.rna.tf32.f32 %0, %1;" : "=f"(x) : "f"(x));
    return x;
}

#define MMA_TF32(c, a, b0_, b1_) \
    asm volatile("mma.sync.aligned.m16n8k8.row.col.f32.tf32.tf32.f32 " \
                 "{%0,%1,%2,%3}, {%4,%5,%6,%7}, {%8,%9}, {%0,%1,%2,%3};" \
                 : "+f"((c)[0]), "+f"((c)[1]), "+f"((c)[2]), "+f"((c)[3]) \
                 : "r"((a)[0]), "r"((a)[1]), "r"((a)[2]), "r"((a)[3]), \
                   "r"(b0_), "r"(b1_))

__device__ __forceinline__ void cp16(uint32_t dst, const void* src) {
    asm volatile("cp.async.ca.shared.global [%0], [%1], 16;" :: "r"(dst), "l"(src));
}
__device__ __forceinline__ uint32_t smem_u32(const void* p) {
    uint32_t a;
    asm("{ .reg .u64 t; cvta.to.shared.u64 t, %1; cvt.u32.u64 %0, t; }" : "=r"(a) : "l"(p));
    return a;
}

// ---------------- tf32 pre-rounding pass (all 5 tensors, one launch) --------
__global__ void cvt_all_kernel(const float4* __restrict__ s0, float4* __restrict__ d0, int n0,
                               const float4* __restrict__ s1, float4* __restrict__ d1, int n1,
                               const float4* __restrict__ s2, float4* __restrict__ d2, int n2,
                               const float4* __restrict__ s3, float4* __restrict__ d3, int n3,
                               const float4* __restrict__ s4, float4* __restrict__ d4, int n4) {
    const int stride = gridDim.x * blockDim.x;
    const int gid = blockIdx.x * blockDim.x + threadIdx.x;
#define CVT_SEG(S, D, N) \
    for (int i = gid; i < (N); i += stride) { \
        float4 v = (S)[i]; \
        v.x = to_tf32(v.x); v.y = to_tf32(v.y); \
        v.z = to_tf32(v.z); v.w = to_tf32(v.w); \
        (D)[i] = v; \
    }
    CVT_SEG(s0, d0, n0)
    CVT_SEG(s1, d1, n1)
    CVT_SEG(s2, d2, n2)
    CVT_SEG(s3, d3, n3)
    CVT_SEG(s4, d4, n4)
#undef CVT_SEG
}

// ============ tf32 tensor GEMM core (pre-rounded operands) ==================
// 128x128 CTA tile, 4 warps (128 thr), warp tile 64x64 -> 1.0 LDS per MMA.
// BK=32, 3-stage cp.async pipeline, occ 2.
#define BK 32
#define LDS_PAD 36
#define STAGE_F (128 * LDS_PAD)
#define STAGES 3
#define GEMM_SMEM (STAGES * 2 * STAGE_F * 4)     // 110592 B

__device__ __forceinline__ void gemm_tile(const float* __restrict__ A,
                                          const float* __restrict__ Bm,
                                          float* __restrict__ C,
                                          int N, int K, int m0, int n0,
                                          float* smem) {
    const uint32_t sb = smem_u32(smem);
    const int tid = threadIdx.x;      // 0..127
    const int wid = tid >> 5;         // 0..3
    const int lane = tid & 31;
    const int g   = lane >> 2;
    const int tig = lane & 3;
    const int wm0 = (wid >> 1) * 64;  // warp M origin (0/64)
    const int wn0 = (wid & 1) * 64;   // warp N origin (0/64)

    float acc[4][8][4];
#pragma unroll
    for (int mt = 0; mt < 4; mt++)
#pragma unroll
        for (int nt = 0; nt < 8; nt++)
#pragma unroll
            for (int r = 0; r < 4; r++) acc[mt][nt][r] = 0.f;

    const int NITER = K / BK;

    // 1024 16B-chunks per matrix per stage; 128 threads -> 8 chunks each
    auto issue_stage = [&](int kt, int s) {
        const int k0 = kt * BK;
        const uint32_t abase = sb + (uint32_t)(s * 2 * STAGE_F) * 4u;
        const uint32_t bbase = abase + (uint32_t)STAGE_F * 4u;
#pragma unroll
        for (int t = 0; t < 8; t++) {
            const int e = tid + t * 128;     // 0..1023
            const int r = e >> 3;            // row 0..127
            const int c = (e & 7) * 4;       // float col 0..28
            const uint32_t soff = (uint32_t)(r * LDS_PAD + c) * 4u;
            cp16(abase + soff, A  + (size_t)(m0 + r) * K + k0 + c);
            cp16(bbase + soff, Bm + (size_t)(n0 + r) * K + k0 + c);
        }
    };

#pragma unroll
    for (int s = 0; s < STAGES - 1; s++) {
        if (s < NITER) issue_stage(s, s);
        asm volatile("cp.async.commit_group;");
    }

    for (int i = 0; i < NITER; i++) {
        asm volatile("cp.async.wait_group %0;" :: "n"(STAGES - 2));
        __syncthreads();

        const float* As = smem + (i % STAGES) * 2 * STAGE_F;
        const float* Bs = As + STAGE_F;
#pragma unroll
        for (int ks = 0; ks < 4; ks++) {
            const int k = ks * 8;
            uint32_t af[4][4], bf[8][2];
#pragma unroll
            for (int mt = 0; mt < 4; mt++) {
                const int am = wm0 + mt * 16 + g;
                af[mt][0] = __float_as_uint(As[(am)     * LDS_PAD + k + tig]);
                af[mt][1] = __float_as_uint(As[(am + 8) * LDS_PAD + k + tig]);
                af[mt][2] = __float_as_uint(As[(am)     * LDS_PAD + k + tig + 4]);
                af[mt][3] = __float_as_uint(As[(am + 8) * LDS_PAD + k + tig + 4]);
            }
#pragma unroll
            for (int nt = 0; nt < 8; nt++) {
                const int bn = wn0 + nt * 8 + g;
                bf[nt][0] = __float_as_uint(Bs[bn * LDS_PAD + k + tig]);
                bf[nt][1] = __float_as_uint(Bs[bn * LDS_PAD + k + tig + 4]);
            }
#pragma unroll
            for (int mt = 0; mt < 4; mt++)
#pragma unroll
                for (int nt = 0; nt < 8; nt++)
                    MMA_TF32(acc[mt][nt], af[mt], bf[nt][0], bf[nt][1]);
        }

        if (i + STAGES - 1 < NITER) issue_stage(i + STAGES - 1, (i + STAGES - 1) % STAGES);
        asm volatile("cp.async.commit_group;");
    }

#pragma unroll
    for (int mt = 0; mt < 4; mt++) {
        const int row = m0 + wm0 + mt * 16 + g;
#pragma unroll
        for (int nt = 0; nt < 8; nt++) {
            const int col = n0 + wn0 + nt * 8 + tig * 2;
            const float* c = acc[mt][nt];
            *reinterpret_cast<float2*>(C + (size_t)row * N + col) = make_float2(c[0], c[1]);
            *reinterpret_cast<float2*>(C + (size_t)(row + 8) * N + col) = make_float2(c[2], c[3]);
        }
    }
}

// Q + K + V projections in one launch. bid 0..511 -> Q, 512..639 -> K, 640..767 -> V.
__global__ void __launch_bounds__(128, 2)
gemm_qkv(const float* __restrict__ A,
         const float* __restrict__ Bq, float* __restrict__ Cq,
         const float* __restrict__ Bk, float* __restrict__ Ck,
         const float* __restrict__ Bv, float* __restrict__ Cv) {
    extern __shared__ float smem[];
    const int bid = blockIdx.x;
    if (bid < 512) {
        gemm_tile(A, Bq, Cq, DM, DM, (bid >> 4) * 128, (bid & 15) * 128, smem);
    } else if (bid < 640) {
        const int t = bid - 512;
        gemm_tile(A, Bk, Ck, NKV * HD, DM, (t >> 2) * 128, (t & 3) * 128, smem);
    } else {
        const int t = bid - 640;
        gemm_tile(A, Bv, Cv, NKV * HD, DM, (t >> 2) * 128, (t & 3) * 128, smem);
    }
}

// O projection (single matrix)
__global__ void __launch_bounds__(128, 2)
gemm_single(const float* __restrict__ A, const float* __restrict__ Bm,
            float* __restrict__ C, int N, int K) {
    extern __shared__ float smem[];
    gemm_tile(A, Bm, C, N, K, blockIdx.y * 128, blockIdx.x * 128, smem);
}

// ---------------- RoPE (q and k in one launch) ------------------------------
__global__ void rope_all(float* __restrict__ q, float* __restrict__ k,
                         int tq, int total) {
    int idx = blockIdx.x * blockDim.x + threadIdx.x;
    if (idx >= total) return;
    float* buf;
    int nheads;
    if (idx < tq) { buf = q; nheads = NH; }
    else          { idx -= tq; buf = k; nheads = NKV; }
    int d   = idx & 31;
    int h   = (idx >> 5) % nheads;
    int row = idx / (32 * nheads);
    int s   = row & (SEQ - 1);
    float inv = expf(-(float)d * (9.210340371976184f / 32.0f));
    float ang = (float)s * inv;
    float c  = cosf(ang);
    float si = sinf(ang);
    float* p = buf + (size_t)row * (nheads * HD) + h * HD;
    float x1 = p[d];
    float x2 = p[d + 32];
    p[d]      = x1 * c - x2 * si;
    p[d + 32] = x2 * c + x1 * si;
}

// ======== causal GQA flash attention: 128 q-rows/block, 32 q-rows/warp ======
#define APAD 68
#define ATTN_SMEM ((64 + 64 + 128) * APAD * 4)   // Ks, Vs, Ps(128 rows) = 69632 B

__global__ void __launch_bounds__(128)
attn_mma(const float* __restrict__ Q, const float* __restrict__ K,
         const float* __restrict__ V, float* __restrict__ O) {
    extern __shared__ float sm[];
    float* Ks = sm;
    float* Vs = sm + 64 * APAD;
    float* Ps = sm + 2 * 64 * APAD;   // 128 rows

    const int qb = (int)gridDim.x - 1 - (int)blockIdx.x;   // longest-first
    const int bh = blockIdx.y;
    const int b   = bh >> 5;
    const int h   = bh & 31;
    const int kvh = h >> 2;
    const int tid = threadIdx.x;
    const int wid = tid >> 5;
    const int lane = tid & 31;
    const int g   = lane >> 2;
    const int tig = lane & 3;
    const int q0 = qb * 128;
    const int wr = wid * 32;

#pragma unroll
    for (int t = 0; t < 16; t++) {
        int e = tid + t * 128;
        int r = e >> 4;
        int c = (e & 15) * 4;
        float4 v = *reinterpret_cast<const float4*>(
            Q + (size_t)(b * SEQ + q0 + r) * DM + h * HD + c);
        *reinterpret_cast<float4*>(&Ps[r * APAD + c]) = v;
    }
    __syncthreads();
    uint32_t qa[2][8][4];
#pragma unroll
    for (int mt = 0; mt < 2; mt++) {
        const int r0 = wr + mt * 16 + g, r1 = r0 + 8;
#pragma unroll
        for (int ks = 0; ks < 8; ks++) {
            const int c0 = ks * 8 + tig, c1 = c0 + 4;
            qa[mt][ks][0] = __float_as_uint(to_tf32(Ps[r0 * APAD + c0]));
            qa[mt][ks][1] = __float_as_uint(to_tf32(Ps[r1 * APAD + c0]));
            qa[mt][ks][2] = __float_as_uint(to_tf32(Ps[r0 * APAD + c1]));
            qa[mt][ks][3] = __float_as_uint(to_tf32(Ps[r1 * APAD + c1]));
        }
    }
    __syncthreads();

    float oc[2][8][4];
#pragma unroll
    for (int mt = 0; mt < 2; mt++)
#pragma unroll
        for (int nt = 0; nt < 8; nt++)
#pragma unroll
            for (int r = 0; r < 4; r++) oc[mt][nt][r] = 0.f;
    float mrow[2][2] = {{-1e30f, -1e30f}, {-1e30f, -1e30f}};
    float lrow[2][2] = {{0.f, 0.f}, {0.f, 0.f}};

    const int nkt = 2 * qb + 2;
    for (int kt = 0; kt < nkt; kt++) {
        __syncthreads();
#pragma unroll
        for (int t = 0; t < 8; t++) {
            int e = tid + t * 128;
            int r = e >> 4;
            int c = (e & 15) * 4;
            size_t go = (size_t)(b * SEQ + kt * 64 + r) * (NKV * HD) + kvh * HD + c;
            float4 kv = *reinterpret_cast<const float4*>(K + go);
            kv.x = to_tf32(kv.x); kv.y = to_tf32(kv.y);
            kv.z = to_tf32(kv.z); kv.w = to_tf32(kv.w);
            *reinterpret_cast<float4*>(&Ks[r * APAD + c]) = kv;
            float4 vv = *reinterpret_cast<const float4*>(V + go);
            vv.x = to_tf32(vv.x); vv.y = to_tf32(vv.y);
            vv.z = to_tf32(vv.z); vv.w = to_tf32(vv.w);
            *reinterpret_cast<float4*>(&Vs[r * APAD + c]) = vv;
        }
        __syncthreads();

        float sc[2][8][4];
#pragma unroll
        for (int mt = 0; mt < 2; mt++)
#pragma unroll
            for (int nt = 0; nt < 8; nt++)
#pragma unroll
                for (int r = 0; r < 4; r++) sc[mt][nt][r] = 0.f;
#pragma unroll
        for (int ks = 0; ks < 8; ks++) {
#pragma unroll
            for (int nt = 0; nt < 8; nt++) {
                const int key = nt * 8 + g;
                uint32_t b0 = __float_as_uint(Ks[key * APAD + ks * 8 + tig]);
                uint32_t b1 = __float_as_uint(Ks[key * APAD + ks * 8 + tig + 4]);
                MMA_TF32(sc[0][nt], qa[0][ks], b0, b1);
                MMA_TF32(sc[1][nt], qa[1][ks], b0, b1);
            }
        }

        const bool tail = (kt >= 2 * qb);
#pragma unroll
        for (int mt = 0; mt < 2; mt++) {
            const int row0 = wr + mt * 16 + g, row1 = row0 + 8;
            const int gr0 = q0 + row0, gr1 = q0 + row1;
            float rm0 = -1e30f, rm1 = -1e30f;
#pragma unroll
            for (int nt = 0; nt < 8; nt++) {
                const int gc0 = kt * 64 + nt * 8 + tig * 2, gc1 = gc0 + 1;
                float s0 = sc[mt][nt][0] * 0.125f; if (tail && gc0 > gr0) s0 = -1e30f;
                float s1 = sc[mt][nt][1] * 0.125f; if (tail && gc1 > gr0) s1 = -1e30f;
                float s2 = sc[mt][nt][2] * 0.125f; if (tail && gc0 > gr1) s2 = -1e30f;
                float s3 = sc[mt][nt][3] * 0.125f; if (tail && gc1 > gr1) s3 = -1e30f;
                sc[mt][nt][0] = s0; sc[mt][nt][1] = s1;
                sc[mt][nt][2] = s2; sc[mt][nt][3] = s3;
                rm0 = fmaxf(rm0, fmaxf(s0, s1));
                rm1 = fmaxf(rm1, fmaxf(s2, s3));
            }
            rm0 = fmaxf(rm0, __shfl_xor_sync(0xFFFFFFFFu, rm0, 1));
            rm0 = fmaxf(rm0, __shfl_xor_sync(0xFFFFFFFFu, rm0, 2));
            rm1 = fmaxf(rm1, __shfl_xor_sync(0xFFFFFFFFu, rm1, 1));
            rm1 = fmaxf(rm1, __shfl_xor_sync(0xFFFFFFFFu, rm1, 2));

            const float mn0 = fmaxf(mrow[mt][0], rm0), mn1 = fmaxf(mrow[mt][1], rm1);
            const float corr0 = __expf(mrow[mt][0] - mn0), corr1 = __expf(mrow[mt][1] - mn1);
            mrow[mt][0] = mn0; mrow[mt][1] = mn1;

            float rs0 = 0.f, rs1 = 0.f;
#pragma unroll
            for (int nt = 0; nt < 8; nt++) {
                float p0 = __expf(sc[mt][nt][0] - mn0);
                float p1 = __expf(sc[mt][nt][1] - mn0);
                float p2 = __expf(sc[mt][nt][2] - mn1);
                float p3 = __expf(sc[mt][nt][3] - mn1);
                rs0 += p0 + p1; rs1 += p2 + p3;
                oc[mt][nt][0] *= corr0; oc[mt][nt][1] *= corr0;
                oc[mt][nt][2] *= corr1; oc[mt][nt][3] *= corr1;
                *reinterpret_cast<float2*>(&Ps[row0 * APAD + nt * 8 + tig * 2]) =
                    make_float2(to_tf32(p0), to_tf32(p1));
                *reinterpret_cast<float2*>(&Ps[row1 * APAD + nt * 8 + tig * 2]) =
                    make_float2(to_tf32(p2), to_tf32(p3));
            }
            rs0 += __shfl_xor_sync(0xFFFFFFFFu, rs0, 1);
            rs0 += __shfl_xor_sync(0xFFFFFFFFu, rs0, 2);
            rs1 += __shfl_xor_sync(0xFFFFFFFFu, rs1, 1);
            rs1 += __shfl_xor_sync(0xFFFFFFFFu, rs1, 2);
            lrow[mt][0] = lrow[mt][0] * corr0 + rs0;
            lrow[mt][1] = lrow[mt][1] * corr1 + rs1;
        }
        __syncwarp();

#pragma unroll
        for (int ks = 0; ks < 8; ks++) {
            uint32_t pa[2][4];
#pragma unroll
            for (int mt = 0; mt < 2; mt++) {
                const int row0 = wr + mt * 16 + g, row1 = row0 + 8;
                pa[mt][0] = __float_as_uint(Ps[row0 * APAD + ks * 8 + tig]);
                pa[mt][1] = __float_as_uint(Ps[row1 * APAD + ks * 8 + tig]);
                pa[mt][2] = __float_as_uint(Ps[row0 * APAD + ks * 8 + tig + 4]);
                pa[mt][3] = __float_as_uint(Ps[row1 * APAD + ks * 8 + tig + 4]);
            }
#pragma unroll
            for (int nt = 0; nt < 8; nt++) {
                uint32_t b0 = __float_as_uint(Vs[(ks * 8 + tig) * APAD + nt * 8 + g]);
                uint32_t b1 = __float_as_uint(Vs[(ks * 8 + tig + 4) * APAD + nt * 8 + g]);
                MMA_TF32(oc[0][nt], pa[0], b0, b1);
                MMA_TF32(oc[1][nt], pa[1], b0, b1);
            }
        }
        __syncwarp();
    }

#pragma unroll
    for (int mt = 0; mt < 2; mt++) {
        const float inv0 = 1.0f / lrow[mt][0], inv1 = 1.0f / lrow[mt][1];
        const size_t gr0 = (size_t)(b * SEQ + q0 + wr + mt * 16 + g);
#pragma unroll
        for (int nt = 0; nt < 8; nt++) {
            const int col = h * HD + nt * 8 + tig * 2;
            *reinterpret_cast<float2*>(O + gr0 * DM + col) =
                make_float2(to_tf32(oc[mt][nt][0] * inv0), to_tf32(oc[mt][nt][1] * inv0));
            *reinterpret_cast<float2*>(O + (gr0 + 8) * DM + col) =
                make_float2(to_tf32(oc[mt][nt][2] * inv1), to_tf32(oc[mt][nt][3] * inv1));
        }
    }
}

// ---------------- launch ----------------------------------------------------
extern "C" void kernel_launch(void* const* d_in, const int* in_sizes, int n_in,
                              void* d_out, int out_size) {
    const float* x  = (const float*)d_in[0];
    const float* Wq = (const float*)d_in[1];
    const float* Wk = (const float*)d_in[2];
    const float* Wv = (const float*)d_in[3];
    const float* Wo = (const float*)d_in[4];
    float* out = (float*)d_out;

    float *gq, *gk, *gv, *go, *xt, *wq, *wk, *wv, *wo;
    cudaGetSymbolAddress((void**)&gq, g_q);
    cudaGetSymbolAddress((void**)&gk, g_k);
    cudaGetSymbolAddress((void**)&gv, g_v);
    cudaGetSymbolAddress((void**)&go, g_o);
    cudaGetSymbolAddress((void**)&xt, g_xt);
    cudaGetSymbolAddress((void**)&wq, g_wq);
    cudaGetSymbolAddress((void**)&wk, g_wk);
    cudaGetSymbolAddress((void**)&wv, g_wv);
    cudaGetSymbolAddress((void**)&wo, g_wo);

    static bool attr_set = false;
    if (!attr_set) {
        cudaFuncSetAttribute(gemm_qkv, cudaFuncAttributeMaxDynamicSharedMemorySize, GEMM_SMEM);
        cudaFuncSetAttribute(gemm_single, cudaFuncAttributeMaxDynamicSharedMemorySize, GEMM_SMEM);
        cudaFuncSetAttribute(attn_mma, cudaFuncAttributeMaxDynamicSharedMemorySize, ATTN_SMEM);
        attr_set = true;
    }

    // pre-round all operands to tf32 values (one launch)
    cvt_all_kernel<<<1184, 256>>>(
        (const float4*)x,  (float4*)xt, (int)((size_t)NT * DM / 4),
        (const float4*)Wq, (float4*)wq, (int)((size_t)DM * DM / 4),
        (const float4*)Wk, (float4*)wk, (int)((size_t)(NKV * HD) * DM / 4),
        (const float4*)Wv, (float4*)wv, (int)((size_t)(NKV * HD) * DM / 4),
        (const float4*)Wo, (float4*)wo, (int)((size_t)DM * DM / 4));

    // Q + K + V projections, one launch (768 CTAs, 128 threads)
    gemm_qkv<<<768, 128, GEMM_SMEM>>>(xt, wq, gq, wk, gk, wv, gv);

    // RoPE on q and k, one launch
    int tq = NT * NH * 32;
    int tk = NT * NKV * 32;
    rope_all<<<(tq + tk + 255) / 256, 256>>>(gq, gk, tq, tq + tk);

    // causal GQA attention (tf32 mma flash, 128 q-rows/block, longest-first)
    attn_mma<<<dim3(SEQ / 128, B_SZ * NH), 128, ATTN_SMEM>>>(gq, gk, gv, go);

    // output projection into d_out
    gemm_single<<<dim3(DM / 128, NT / 128), 128, GEMM_SMEM>>>(go, wo, out, DM, DM);
}

// round 14
// speedup vs baseline: 1.9795x; 1.9795x over previous
#include <cuda_runtime.h>
#include <cuda_fp16.h>
#include <cstdint>

#define B_SZ   2
#define SEQ    2048
#define DM     2048
#define NH     32
#define NKV    8
#define HD     64
#define NT     (B_SZ * SEQ)   // 4096 tokens

// ---------------- scratch (static device globals; no runtime allocation) ----
__device__ float  g_q[(size_t)NT * DM];           // 32 MB (fp32, feeds attention)
__device__ float  g_k[(size_t)NT * NKV * HD];     //  8 MB
__device__ float  g_v[(size_t)NT * NKV * HD];     //  8 MB
__device__ __half g_oh[(size_t)NT * DM];          // 16 MB (attention out, fp16)
__device__ __half g_xh[(size_t)NT * DM];          // 16 MB (fp16 operand copies)
__device__ __half g_wqh[(size_t)DM * DM];         //  8 MB
__device__ __half g_wkh[(size_t)(NKV * HD) * DM]; //  2 MB
__device__ __half g_wvh[(size_t)(NKV * HD) * DM]; //  2 MB
__device__ __half g_woh[(size_t)DM * DM];         //  8 MB

__device__ __forceinline__ float to_tf32(float x) {
    asm("cvt.rna.tf32.f32 %0, %1;" : "=f"(x) : "f"(x));
    return x;
}

#define MMA_TF32(c, a, b0_, b1_) \
    asm volatile("mma.sync.aligned.m16n8k8.row.col.f32.tf32.tf32.f32 " \
                 "{%0,%1,%2,%3}, {%4,%5,%6,%7}, {%8,%9}, {%0,%1,%2,%3};" \
                 : "+f"((c)[0]), "+f"((c)[1]), "+f"((c)[2]), "+f"((c)[3]) \
                 : "r"((a)[0]), "r"((a)[1]), "r"((a)[2]), "r"((a)[3]), \
                   "r"(b0_), "r"(b1_))

#define MMA_F16(c, a, b0_, b1_) \
    asm volatile("mma.sync.aligned.m16n8k16.row.col.f32.f16.f16.f32 " \
                 "{%0,%1,%2,%3}, {%4,%5,%6,%7}, {%8,%9}, {%0,%1,%2,%3};" \
                 : "+f"((c)[0]), "+f"((c)[1]), "+f"((c)[2]), "+f"((c)[3]) \
                 : "r"((a)[0]), "r"((a)[1]), "r"((a)[2]), "r"((a)[3]), \
                   "r"(b0_), "r"(b1_))

__device__ __forceinline__ void cp16(uint32_t dst, const void* src) {
    asm volatile("cp.async.ca.shared.global [%0], [%1], 16;" :: "r"(dst), "l"(src));
}
__device__ __forceinline__ uint32_t smem_u32(const void* p) {
    uint32_t a;
    asm("{ .reg .u64 t; cvta.to.shared.u64 t, %1; cvt.u32.u64 %0, t; }" : "=r"(a) : "l"(p));
    return a;
}

// ---------------- fp16 pre-rounding pass (all 5 tensors, one launch) --------
__global__ void cvt_all_kernel(const float4* __restrict__ s0, uint2* __restrict__ d0, int n0,
                               const float4* __restrict__ s1, uint2* __restrict__ d1, int n1,
                               const float4* __restrict__ s2, uint2* __restrict__ d2, int n2,
                               const float4* __restrict__ s3, uint2* __restrict__ d3, int n3,
                               const float4* __restrict__ s4, uint2* __restrict__ d4, int n4) {
    const int stride = gridDim.x * blockDim.x;
    const int gid = blockIdx.x * blockDim.x + threadIdx.x;
#define CVT_SEG(S, D, N) \
    for (int i = gid; i < (N); i += stride) { \
        float4 v = (S)[i]; \
        __half2 h01 = __floats2half2_rn(v.x, v.y); \
        __half2 h23 = __floats2half2_rn(v.z, v.w); \
        uint2 u; \
        u.x = *reinterpret_cast<uint32_t*>(&h01); \
        u.y = *reinterpret_cast<uint32_t*>(&h23); \
        (D)[i] = u; \
    }
    CVT_SEG(s0, d0, n0)
    CVT_SEG(s1, d1, n1)
    CVT_SEG(s2, d2, n2)
    CVT_SEG(s3, d3, n3)
    CVT_SEG(s4, d4, n4)
#undef CVT_SEG
}

// ============ fp16 tensor GEMM: C[M,N] = A[M,K] * B[N,K]^T ==================
// 128x128 CTA tile, 8 warps (256 thr), warp tile 32x64, k16 MMAs.
// BK=32 (2 k16 steps), 3-stage cp.async pipeline, occ 2.
#define BK 32
#define PADH 40                                   // halves per row (80 B)
#define STAGE_H (128 * PADH)                      // halves per matrix per stage
#define STAGES 3
#define GEMM_SMEM (STAGES * 2 * STAGE_H * 2)      // 61440 B

__device__ __forceinline__ void gemm_tile(const __half* __restrict__ A,
                                          const __half* __restrict__ Bm,
                                          float* __restrict__ C,
                                          int N, int K, int m0, int n0,
                                          __half* smem) {
    const uint32_t sb = smem_u32(smem);
    const int tid = threadIdx.x;
    const int wid = tid >> 5;
    const int lane = tid & 31;
    const int g   = lane >> 2;
    const int tig = lane & 3;
    const int wm0 = (wid & 3) * 32;
    const int wn0 = (wid >> 2) * 64;

    float acc[2][8][4];
#pragma unroll
    for (int mt = 0; mt < 2; mt++)
#pragma unroll
        for (int nt = 0; nt < 8; nt++)
#pragma unroll
            for (int r = 0; r < 4; r++) acc[mt][nt][r] = 0.f;

    const int NITER = K / BK;

    // 512 16B-chunks (8 halves) per matrix per stage; 256 threads -> 2 each
    auto issue_stage = [&](int kt, int s) {
        const int k0 = kt * BK;
        const uint32_t abase = sb + (uint32_t)(s * 2 * STAGE_H) * 2u;
        const uint32_t bbase = abase + (uint32_t)STAGE_H * 2u;
#pragma unroll
        for (int t = 0; t < 2; t++) {
            const int e = tid + t * 256;     // 0..511
            const int r = e >> 2;            // row 0..127
            const int c = (e & 3) * 8;       // half col 0,8,16,24
            const uint32_t soff = (uint32_t)(r * PADH + c) * 2u;
            cp16(abase + soff, A  + (size_t)(m0 + r) * K + k0 + c);
            cp16(bbase + soff, Bm + (size_t)(n0 + r) * K + k0 + c);
        }
    };

#pragma unroll
    for (int s = 0; s < STAGES - 1; s++) {
        if (s < NITER) issue_stage(s, s);
        asm volatile("cp.async.commit_group;");
    }

    for (int i = 0; i < NITER; i++) {
        asm volatile("cp.async.wait_group %0;" :: "n"(STAGES - 2));
        __syncthreads();

        const __half* As = smem + (i % STAGES) * 2 * STAGE_H;
        const __half* Bs = As + STAGE_H;
#pragma unroll
        for (int step = 0; step < 2; step++) {
            const int kk = step * 16;
            uint32_t af[2][4], bf[8][2];
#pragma unroll
            for (int mt = 0; mt < 2; mt++) {
                const int am = wm0 + mt * 16 + g;
                af[mt][0] = *reinterpret_cast<const uint32_t*>(&As[(am)     * PADH + kk + 2 * tig]);
                af[mt][1] = *reinterpret_cast<const uint32_t*>(&As[(am + 8) * PADH + kk + 2 * tig]);
                af[mt][2] = *reinterpret_cast<const uint32_t*>(&As[(am)     * PADH + kk + 2 * tig + 8]);
                af[mt][3] = *reinterpret_cast<const uint32_t*>(&As[(am + 8) * PADH + kk + 2 * tig + 8]);
            }
#pragma unroll
            for (int nt = 0; nt < 8; nt++) {
                const int bn = wn0 + nt * 8 + g;
                bf[nt][0] = *reinterpret_cast<const uint32_t*>(&Bs[bn * PADH + kk + 2 * tig]);
                bf[nt][1] = *reinterpret_cast<const uint32_t*>(&Bs[bn * PADH + kk + 2 * tig + 8]);
            }
#pragma unroll
            for (int mt = 0; mt < 2; mt++)
#pragma unroll
                for (int nt = 0; nt < 8; nt++)
                    MMA_F16(acc[mt][nt], af[mt], bf[nt][0], bf[nt][1]);
        }

        if (i + STAGES - 1 < NITER) issue_stage(i + STAGES - 1, (i + STAGES - 1) % STAGES);
        asm volatile("cp.async.commit_group;");
    }

#pragma unroll
    for (int mt = 0; mt < 2; mt++) {
        const int row = m0 + wm0 + mt * 16 + g;
#pragma unroll
        for (int nt = 0; nt < 8; nt++) {
            const int col = n0 + wn0 + nt * 8 + tig * 2;
            const float* c = acc[mt][nt];
            *reinterpret_cast<float2*>(C + (size_t)row * N + col) = make_float2(c[0], c[1]);
            *reinterpret_cast<float2*>(C + (size_t)(row + 8) * N + col) = make_float2(c[2], c[3]);
        }
    }
}

// Q + K + V projections in one launch. bid 0..511 -> Q, 512..639 -> K, 640..767 -> V.
__global__ void __launch_bounds__(256, 2)
gemm_qkv(const __half* __restrict__ A,
         const __half* __restrict__ Bq, float* __restrict__ Cq,
         const __half* __restrict__ Bk, float* __restrict__ Ck,
         const __half* __restrict__ Bv, float* __restrict__ Cv) {
    extern __shared__ __half smemh[];
    const int bid = blockIdx.x;
    if (bid < 512) {
        gemm_tile(A, Bq, Cq, DM, DM, (bid >> 4) * 128, (bid & 15) * 128, smemh);
    } else if (bid < 640) {
        const int t = bid - 512;
        gemm_tile(A, Bk, Ck, NKV * HD, DM, (t >> 2) * 128, (t & 3) * 128, smemh);
    } else {
        const int t = bid - 640;
        gemm_tile(A, Bv, Cv, NKV * HD, DM, (t >> 2) * 128, (t & 3) * 128, smemh);
    }
}

// O projection (single matrix)
__global__ void __launch_bounds__(256, 2)
gemm_single(const __half* __restrict__ A, const __half* __restrict__ Bm,
            float* __restrict__ C, int N, int K) {
    extern __shared__ __half smemh[];
    gemm_tile(A, Bm, C, N, K, blockIdx.y * 128, blockIdx.x * 128, smemh);
}

// ---------------- RoPE (q and k in one launch) ------------------------------
__global__ void rope_all(float* __restrict__ q, float* __restrict__ k,
                         int tq, int total) {
    int idx = blockIdx.x * blockDim.x + threadIdx.x;
    if (idx >= total) return;
    float* buf;
    int nheads;
    if (idx < tq) { buf = q; nheads = NH; }
    else          { idx -= tq; buf = k; nheads = NKV; }
    int d   = idx & 31;
    int h   = (idx >> 5) % nheads;
    int row = idx / (32 * nheads);
    int s   = row & (SEQ - 1);
    float inv = expf(-(float)d * (9.210340371976184f / 32.0f));
    float ang = (float)s * inv;
    float c  = cosf(ang);
    float si = sinf(ang);
    float* p = buf + (size_t)row * (nheads * HD) + h * HD;
    float x1 = p[d];
    float x2 = p[d + 32];
    p[d]      = x1 * c - x2 * si;
    p[d + 32] = x2 * c + x1 * si;
}

// ======== causal GQA flash attention: 128 q-rows/block, 32 q-rows/warp ======
// (R12 kernel; only the final store now emits fp16 for the O-projection.)
#define APAD 68
#define ATTN_SMEM ((64 + 64 + 128) * APAD * 4)   // Ks, Vs, Ps(128 rows) = 69632 B

__global__ void __launch_bounds__(128)
attn_mma(const float* __restrict__ Q, const float* __restrict__ K,
         const float* __restrict__ V, __half* __restrict__ O) {
    extern __shared__ float sm[];
    float* Ks = sm;
    float* Vs = sm + 64 * APAD;
    float* Ps = sm + 2 * 64 * APAD;   // 128 rows

    const int qb = (int)gridDim.x - 1 - (int)blockIdx.x;   // longest-first
    const int bh = blockIdx.y;
    const int b   = bh >> 5;
    const int h   = bh & 31;
    const int kvh = h >> 2;
    const int tid = threadIdx.x;
    const int wid = tid >> 5;
    const int lane = tid & 31;
    const int g   = lane >> 2;
    const int tig = lane & 3;
    const int q0 = qb * 128;
    const int wr = wid * 32;

#pragma unroll
    for (int t = 0; t < 16; t++) {
        int e = tid + t * 128;
        int r = e >> 4;
        int c = (e & 15) * 4;
        float4 v = *reinterpret_cast<const float4*>(
            Q + (size_t)(b * SEQ + q0 + r) * DM + h * HD + c);
        *reinterpret_cast<float4*>(&Ps[r * APAD + c]) = v;
    }
    __syncthreads();
    uint32_t qa[2][8][4];
#pragma unroll
    for (int mt = 0; mt < 2; mt++) {
        const int r0 = wr + mt * 16 + g, r1 = r0 + 8;
#pragma unroll
        for (int ks = 0; ks < 8; ks++) {
            const int c0 = ks * 8 + tig, c1 = c0 + 4;
            qa[mt][ks][0] = __float_as_uint(to_tf32(Ps[r0 * APAD + c0]));
            qa[mt][ks][1] = __float_as_uint(to_tf32(Ps[r1 * APAD + c0]));
            qa[mt][ks][2] = __float_as_uint(to_tf32(Ps[r0 * APAD + c1]));
            qa[mt][ks][3] = __float_as_uint(to_tf32(Ps[r1 * APAD + c1]));
        }
    }
    __syncthreads();

    float oc[2][8][4];
#pragma unroll
    for (int mt = 0; mt < 2; mt++)
#pragma unroll
        for (int nt = 0; nt < 8; nt++)
#pragma unroll
            for (int r = 0; r < 4; r++) oc[mt][nt][r] = 0.f;
    float mrow[2][2] = {{-1e30f, -1e30f}, {-1e30f, -1e30f}};
    float lrow[2][2] = {{0.f, 0.f}, {0.f, 0.f}};

    const int nkt = 2 * qb + 2;
    for (int kt = 0; kt < nkt; kt++) {
        __syncthreads();
#pragma unroll
        for (int t = 0; t < 8; t++) {
            int e = tid + t * 128;
            int r = e >> 4;
            int c = (e & 15) * 4;
            size_t go = (size_t)(b * SEQ + kt * 64 + r) * (NKV * HD) + kvh * HD + c;
            float4 kv = *reinterpret_cast<const float4*>(K + go);
            kv.x = to_tf32(kv.x); kv.y = to_tf32(kv.y);
            kv.z = to_tf32(kv.z); kv.w = to_tf32(kv.w);
            *reinterpret_cast<float4*>(&Ks[r * APAD + c]) = kv;
            float4 vv = *reinterpret_cast<const float4*>(V + go);
            vv.x = to_tf32(vv.x); vv.y = to_tf32(vv.y);
            vv.z = to_tf32(vv.z); vv.w = to_tf32(vv.w);
            *reinterpret_cast<float4*>(&Vs[r * APAD + c]) = vv;
        }
        __syncthreads();

        float sc[2][8][4];
#pragma unroll
        for (int mt = 0; mt < 2; mt++)
#pragma unroll
            for (int nt = 0; nt < 8; nt++)
#pragma unroll
                for (int r = 0; r < 4; r++) sc[mt][nt][r] = 0.f;
#pragma unroll
        for (int ks = 0; ks < 8; ks++) {
#pragma unroll
            for (int nt = 0; nt < 8; nt++) {
                const int key = nt * 8 + g;
                uint32_t b0 = __float_as_uint(Ks[key * APAD + ks * 8 + tig]);
                uint32_t b1 = __float_as_uint(Ks[key * APAD + ks * 8 + tig + 4]);
                MMA_TF32(sc[0][nt], qa[0][ks], b0, b1);
                MMA_TF32(sc[1][nt], qa[1][ks], b0, b1);
            }
        }

        const bool tail = (kt >= 2 * qb);
#pragma unroll
        for (int mt = 0; mt < 2; mt++) {
            const int row0 = wr + mt * 16 + g, row1 = row0 + 8;
            const int gr0 = q0 + row0, gr1 = q0 + row1;
            float rm0 = -1e30f, rm1 = -1e30f;
#pragma unroll
            for (int nt = 0; nt < 8; nt++) {
                const int gc0 = kt * 64 + nt * 8 + tig * 2, gc1 = gc0 + 1;
                float s0 = sc[mt][nt][0] * 0.125f; if (tail && gc0 > gr0) s0 = -1e30f;
                float s1 = sc[mt][nt][1] * 0.125f; if (tail && gc1 > gr0) s1 = -1e30f;
                float s2 = sc[mt][nt][2] * 0.125f; if (tail && gc0 > gr1) s2 = -1e30f;
                float s3 = sc[mt][nt][3] * 0.125f; if (tail && gc1 > gr1) s3 = -1e30f;
                sc[mt][nt][0] = s0; sc[mt][nt][1] = s1;
                sc[mt][nt][2] = s2; sc[mt][nt][3] = s3;
                rm0 = fmaxf(rm0, fmaxf(s0, s1));
                rm1 = fmaxf(rm1, fmaxf(s2, s3));
            }
            rm0 = fmaxf(rm0, __shfl_xor_sync(0xFFFFFFFFu, rm0, 1));
            rm0 = fmaxf(rm0, __shfl_xor_sync(0xFFFFFFFFu, rm0, 2));
            rm1 = fmaxf(rm1, __shfl_xor_sync(0xFFFFFFFFu, rm1, 1));
            rm1 = fmaxf(rm1, __shfl_xor_sync(0xFFFFFFFFu, rm1, 2));

            const float mn0 = fmaxf(mrow[mt][0], rm0), mn1 = fmaxf(mrow[mt][1], rm1);
            const float corr0 = __expf(mrow[mt][0] - mn0), corr1 = __expf(mrow[mt][1] - mn1);
            mrow[mt][0] = mn0; mrow[mt][1] = mn1;

            float rs0 = 0.f, rs1 = 0.f;
#pragma unroll
            for (int nt = 0; nt < 8; nt++) {
                float p0 = __expf(sc[mt][nt][0] - mn0);
                float p1 = __expf(sc[mt][nt][1] - mn0);
                float p2 = __expf(sc[mt][nt][2] - mn1);
                float p3 = __expf(sc[mt][nt][3] - mn1);
                rs0 += p0 + p1; rs1 += p2 + p3;
                oc[mt][nt][0] *= corr0; oc[mt][nt][1] *= corr0;
                oc[mt][nt][2] *= corr1; oc[mt][nt][3] *= corr1;
                *reinterpret_cast<float2*>(&Ps[row0 * APAD + nt * 8 + tig * 2]) =
                    make_float2(to_tf32(p0), to_tf32(p1));
                *reinterpret_cast<float2*>(&Ps[row1 * APAD + nt * 8 + tig * 2]) =
                    make_float2(to_tf32(p2), to_tf32(p3));
            }
            rs0 += __shfl_xor_sync(0xFFFFFFFFu, rs0, 1);
            rs0 += __shfl_xor_sync(0xFFFFFFFFu, rs0, 2);
            rs1 += __shfl_xor_sync(0xFFFFFFFFu, rs1, 1);
            rs1 += __shfl_xor_sync(0xFFFFFFFFu, rs1, 2);
            lrow[mt][0] = lrow[mt][0] * corr0 + rs0;
            lrow[mt][1] = lrow[mt][1] * corr1 + rs1;
        }
        __syncwarp();

#pragma unroll
        for (int ks = 0; ks < 8; ks++) {
            uint32_t pa[2][4];
#pragma unroll
            for (int mt = 0; mt < 2; mt++) {
                const int row0 = wr + mt * 16 + g, row1 = row0 + 8;
                pa[mt][0] = __float_as_uint(Ps[row0 * APAD + ks * 8 + tig]);
                pa[mt][1] = __float_as_uint(Ps[row1 * APAD + ks * 8 + tig]);
                pa[mt][2] = __float_as_uint(Ps[row0 * APAD + ks * 8 + tig + 4]);
                pa[mt][3] = __float_as_uint(Ps[row1 * APAD + ks * 8 + tig + 4]);
            }
#pragma unroll
            for (int nt = 0; nt < 8; nt++) {
                uint32_t b0 = __float_as_uint(Vs[(ks * 8 + tig) * APAD + nt * 8 + g]);
                uint32_t b1 = __float_as_uint(Vs[(ks * 8 + tig + 4) * APAD + nt * 8 + g]);
                MMA_TF32(oc[0][nt], pa[0], b0, b1);
                MMA_TF32(oc[1][nt], pa[1], b0, b1);
            }
        }
        __syncwarp();
    }

    // ---- finalize: fp16 store (pre-rounds the O-projection A operand) ----
#pragma unroll
    for (int mt = 0; mt < 2; mt++) {
        const float inv0 = 1.0f / lrow[mt][0], inv1 = 1.0f / lrow[mt][1];
        const size_t gr0 = (size_t)(b * SEQ + q0 + wr + mt * 16 + g);
#pragma unroll
        for (int nt = 0; nt < 8; nt++) {
            const int col = h * HD + nt * 8 + tig * 2;
            *reinterpret_cast<__half2*>(O + gr0 * DM + col) =
                __floats2half2_rn(oc[mt][nt][0] * inv0, oc[mt][nt][1] * inv0);
            *reinterpret_cast<__half2*>(O + (gr0 + 8) * DM + col) =
                __floats2half2_rn(oc[mt][nt][2] * inv1, oc[mt][nt][3] * inv1);
        }
    }
}

// ---------------- launch ----------------------------------------------------
extern "C" void kernel_launch(void* const* d_in, const int* in_sizes, int n_in,
                              void* d_out, int out_size) {
    const float* x  = (const float*)d_in[0];
    const float* Wq = (const float*)d_in[1];
    const float* Wk = (const float*)d_in[2];
    const float* Wv = (const float*)d_in[3];
    const float* Wo = (const float*)d_in[4];
    float* out = (float*)d_out;

    float *gq, *gk, *gv;
    __half *oh, *xh, *wqh, *wkh, *wvh, *woh;
    cudaGetSymbolAddress((void**)&gq, g_q);
    cudaGetSymbolAddress((void**)&gk, g_k);
    cudaGetSymbolAddress((void**)&gv, g_v);
    cudaGetSymbolAddress((void**)&oh, g_oh);
    cudaGetSymbolAddress((void**)&xh, g_xh);
    cudaGetSymbolAddress((void**)&wqh, g_wqh);
    cudaGetSymbolAddress((void**)&wkh, g_wkh);
    cudaGetSymbolAddress((void**)&wvh, g_wvh);
    cudaGetSymbolAddress((void**)&woh, g_woh);

    static bool attr_set = false;
    if (!attr_set) {
        cudaFuncSetAttribute(gemm_qkv, cudaFuncAttributeMaxDynamicSharedMemorySize, GEMM_SMEM);
        cudaFuncSetAttribute(gemm_single, cudaFuncAttributeMaxDynamicSharedMemorySize, GEMM_SMEM);
        cudaFuncSetAttribute(attn_mma, cudaFuncAttributeMaxDynamicSharedMemorySize, ATTN_SMEM);
        attr_set = true;
    }

    // pre-round all GEMM operands to fp16 (one launch)
    cvt_all_kernel<<<1184, 256>>>(
        (const float4*)x,  (uint2*)xh,  (int)((size_t)NT * DM / 4),
        (const float4*)Wq, (uint2*)wqh, (int)((size_t)DM * DM / 4),
        (const float4*)Wk, (uint2*)wkh, (int)((size_t)(NKV * HD) * DM / 4),
        (const float4*)Wv, (uint2*)wvh, (int)((size_t)(NKV * HD) * DM / 4),
        (const float4*)Wo, (uint2*)woh, (int)((size_t)DM * DM / 4));

    // Q + K + V projections, one launch (768 CTAs, 256 threads)
    gemm_qkv<<<768, 256, GEMM_SMEM>>>(xh, wqh, gq, wkh, gk, wvh, gv);

    // RoPE on q and k, one launch
    int tq = NT * NH * 32;
    int tk = NT * NKV * 32;
    rope_all<<<(tq + tk + 255) / 256, 256>>>(gq, gk, tq, tq + tk);

    // causal GQA attention (tf32 mma flash, 128 q-rows/block, longest-first)
    attn_mma<<<dim3(SEQ / 128, B_SZ * NH), 128, ATTN_SMEM>>>(gq, gk, gv, oh);

    // output projection into d_out
    gemm_single<<<dim3(DM / 128, NT / 128), 256, GEMM_SMEM>>>(oh, woh, out, DM, DM);
}

// round 15
// speedup vs baseline: 2.1990x; 1.1109x over previous
#include <cuda_runtime.h>
#include <cuda_fp16.h>
#include <cstdint>

#define B_SZ   2
#define SEQ    2048
#define DM     2048
#define NH     32
#define NKV    8
#define HD     64
#define NT     (B_SZ * SEQ)   // 4096 tokens

// ---------------- scratch (static device globals; no runtime allocation) ----
__device__ float  g_q[(size_t)NT * DM];           // fp32, feeds attention
__device__ float  g_k[(size_t)NT * NKV * HD];
__device__ float  g_v[(size_t)NT * NKV * HD];
__device__ __half g_oh[(size_t)NT * DM];          // attention out, fp16
__device__ __half g_xh[(size_t)NT * DM];          // fp16 operand copies
__device__ __half g_wqh[(size_t)DM * DM];
__device__ __half g_wkh[(size_t)(NKV * HD) * DM];
__device__ __half g_wvh[(size_t)(NKV * HD) * DM];
__device__ __half g_woh[(size_t)DM * DM];

#define MMA_F16(c, a, b0_, b1_) \
    asm volatile("mma.sync.aligned.m16n8k16.row.col.f32.f16.f16.f32 " \
                 "{%0,%1,%2,%3}, {%4,%5,%6,%7}, {%8,%9}, {%0,%1,%2,%3};" \
                 : "+f"((c)[0]), "+f"((c)[1]), "+f"((c)[2]), "+f"((c)[3]) \
                 : "r"((a)[0]), "r"((a)[1]), "r"((a)[2]), "r"((a)[3]), \
                   "r"(b0_), "r"(b1_))

__device__ __forceinline__ void cp16(uint32_t dst, const void* src) {
    asm volatile("cp.async.ca.shared.global [%0], [%1], 16;" :: "r"(dst), "l"(src));
}
__device__ __forceinline__ uint32_t smem_u32(const void* p) {
    uint32_t a;
    asm("{ .reg .u64 t; cvta.to.shared.u64 t, %1; cvt.u32.u64 %0, t; }" : "=r"(a) : "l"(p));
    return a;
}
__device__ __forceinline__ uint32_t h2_u32(__half2 h) {
    return *reinterpret_cast<uint32_t*>(&h);
}

// ---------------- fp16 pre-rounding pass (all 5 tensors, one launch) --------
__global__ void cvt_all_kernel(const float4* __restrict__ s0, uint2* __restrict__ d0, int n0,
                               const float4* __restrict__ s1, uint2* __restrict__ d1, int n1,
                               const float4* __restrict__ s2, uint2* __restrict__ d2, int n2,
                               const float4* __restrict__ s3, uint2* __restrict__ d3, int n3,
                               const float4* __restrict__ s4, uint2* __restrict__ d4, int n4) {
    const int stride = gridDim.x * blockDim.x;
    const int gid = blockIdx.x * blockDim.x + threadIdx.x;
#define CVT_SEG(S, D, N) \
    for (int i = gid; i < (N); i += stride) { \
        float4 v = (S)[i]; \
        __half2 h01 = __floats2half2_rn(v.x, v.y); \
        __half2 h23 = __floats2half2_rn(v.z, v.w); \
        uint2 u; \
        u.x = *reinterpret_cast<uint32_t*>(&h01); \
        u.y = *reinterpret_cast<uint32_t*>(&h23); \
        (D)[i] = u; \
    }
    CVT_SEG(s0, d0, n0)
    CVT_SEG(s1, d1, n1)
    CVT_SEG(s2, d2, n2)
    CVT_SEG(s3, d3, n3)
    CVT_SEG(s4, d4, n4)
#undef CVT_SEG
}

// ============ fp16 tensor GEMM: C[M,N] = A[M,K] * B[N,K]^T (R14) ============
#define BK 32
#define PADH 40
#define STAGE_H (128 * PADH)
#define STAGES 3
#define GEMM_SMEM (STAGES * 2 * STAGE_H * 2)      // 61440 B

__device__ __forceinline__ void gemm_tile(const __half* __restrict__ A,
                                          const __half* __restrict__ Bm,
                                          float* __restrict__ C,
                                          int N, int K, int m0, int n0,
                                          __half* smem) {
    const uint32_t sb = smem_u32(smem);
    const int tid = threadIdx.x;
    const int wid = tid >> 5;
    const int lane = tid & 31;
    const int g   = lane >> 2;
    const int tig = lane & 3;
    const int wm0 = (wid & 3) * 32;
    const int wn0 = (wid >> 2) * 64;

    float acc[2][8][4];
#pragma unroll
    for (int mt = 0; mt < 2; mt++)
#pragma unroll
        for (int nt = 0; nt < 8; nt++)
#pragma unroll
            for (int r = 0; r < 4; r++) acc[mt][nt][r] = 0.f;

    const int NITER = K / BK;

    auto issue_stage = [&](int kt, int s) {
        const int k0 = kt * BK;
        const uint32_t abase = sb + (uint32_t)(s * 2 * STAGE_H) * 2u;
        const uint32_t bbase = abase + (uint32_t)STAGE_H * 2u;
#pragma unroll
        for (int t = 0; t < 2; t++) {
            const int e = tid + t * 256;
            const int r = e >> 2;
            const int c = (e & 3) * 8;
            const uint32_t soff = (uint32_t)(r * PADH + c) * 2u;
            cp16(abase + soff, A  + (size_t)(m0 + r) * K + k0 + c);
            cp16(bbase + soff, Bm + (size_t)(n0 + r) * K + k0 + c);
        }
    };

#pragma unroll
    for (int s = 0; s < STAGES - 1; s++) {
        if (s < NITER) issue_stage(s, s);
        asm volatile("cp.async.commit_group;");
    }

    for (int i = 0; i < NITER; i++) {
        asm volatile("cp.async.wait_group %0;" :: "n"(STAGES - 2));
        __syncthreads();

        const __half* As = smem + (i % STAGES) * 2 * STAGE_H;
        const __half* Bs = As + STAGE_H;
#pragma unroll
        for (int step = 0; step < 2; step++) {
            const int kk = step * 16;
            uint32_t af[2][4], bf[8][2];
#pragma unroll
            for (int mt = 0; mt < 2; mt++) {
                const int am = wm0 + mt * 16 + g;
                af[mt][0] = *reinterpret_cast<const uint32_t*>(&As[(am)     * PADH + kk + 2 * tig]);
                af[mt][1] = *reinterpret_cast<const uint32_t*>(&As[(am + 8) * PADH + kk + 2 * tig]);
                af[mt][2] = *reinterpret_cast<const uint32_t*>(&As[(am)     * PADH + kk + 2 * tig + 8]);
                af[mt][3] = *reinterpret_cast<const uint32_t*>(&As[(am + 8) * PADH + kk + 2 * tig + 8]);
            }
#pragma unroll
            for (int nt = 0; nt < 8; nt++) {
                const int bn = wn0 + nt * 8 + g;
                bf[nt][0] = *reinterpret_cast<const uint32_t*>(&Bs[bn * PADH + kk + 2 * tig]);
                bf[nt][1] = *reinterpret_cast<const uint32_t*>(&Bs[bn * PADH + kk + 2 * tig + 8]);
            }
#pragma unroll
            for (int mt = 0; mt < 2; mt++)
#pragma unroll
                for (int nt = 0; nt < 8; nt++)
                    MMA_F16(acc[mt][nt], af[mt], bf[nt][0], bf[nt][1]);
        }

        if (i + STAGES - 1 < NITER) issue_stage(i + STAGES - 1, (i + STAGES - 1) % STAGES);
        asm volatile("cp.async.commit_group;");
    }

#pragma unroll
    for (int mt = 0; mt < 2; mt++) {
        const int row = m0 + wm0 + mt * 16 + g;
#pragma unroll
        for (int nt = 0; nt < 8; nt++) {
            const int col = n0 + wn0 + nt * 8 + tig * 2;
            const float* c = acc[mt][nt];
            *reinterpret_cast<float2*>(C + (size_t)row * N + col) = make_float2(c[0], c[1]);
            *reinterpret_cast<float2*>(C + (size_t)(row + 8) * N + col) = make_float2(c[2], c[3]);
        }
    }
}

__global__ void __launch_bounds__(256, 2)
gemm_qkv(const __half* __restrict__ A,
         const __half* __restrict__ Bq, float* __restrict__ Cq,
         const __half* __restrict__ Bk, float* __restrict__ Ck,
         const __half* __restrict__ Bv, float* __restrict__ Cv) {
    extern __shared__ __half smemh[];
    const int bid = blockIdx.x;
    if (bid < 512) {
        gemm_tile(A, Bq, Cq, DM, DM, (bid >> 4) * 128, (bid & 15) * 128, smemh);
    } else if (bid < 640) {
        const int t = bid - 512;
        gemm_tile(A, Bk, Ck, NKV * HD, DM, (t >> 2) * 128, (t & 3) * 128, smemh);
    } else {
        const int t = bid - 640;
        gemm_tile(A, Bv, Cv, NKV * HD, DM, (t >> 2) * 128, (t & 3) * 128, smemh);
    }
}

__global__ void __launch_bounds__(256, 2)
gemm_single(const __half* __restrict__ A, const __half* __restrict__ Bm,
            float* __restrict__ C, int N, int K) {
    extern __shared__ __half smemh[];
    gemm_tile(A, Bm, C, N, K, blockIdx.y * 128, blockIdx.x * 128, smemh);
}

// ---------------- RoPE (q and k in one launch) ------------------------------
__global__ void rope_all(float* __restrict__ q, float* __restrict__ k,
                         int tq, int total) {
    int idx = blockIdx.x * blockDim.x + threadIdx.x;
    if (idx >= total) return;
    float* buf;
    int nheads;
    if (idx < tq) { buf = q; nheads = NH; }
    else          { idx -= tq; buf = k; nheads = NKV; }
    int d   = idx & 31;
    int h   = (idx >> 5) % nheads;
    int row = idx / (32 * nheads);
    int s   = row & (SEQ - 1);
    float inv = expf(-(float)d * (9.210340371976184f / 32.0f));
    float ang = (float)s * inv;
    float c  = cosf(ang);
    float si = sinf(ang);
    float* p = buf + (size_t)row * (nheads * HD) + h * HD;
    float x1 = p[d];
    float x2 = p[d + 32];
    p[d]      = x1 * c - x2 * si;
    p[d + 32] = x2 * c + x1 * si;
}

// ======== causal GQA flash attention, fp16 mma (m16n8k16) ===================
// 128 q-rows/block, 4 warps, 32 q-rows/warp. K [key][d], V transposed [d][key],
// Q/P share one half buffer [128][HPAD]. fp32 accumulate + softmax.
#define HPAD 72
#define ATTN_SMEM ((2 * 64 * HPAD + 128 * HPAD) * 2)   // 36864 B

__global__ void __launch_bounds__(128)
attn_mma(const float* __restrict__ Q, const float* __restrict__ K,
         const float* __restrict__ V, __half* __restrict__ O) {
    extern __shared__ __half smh[];
    __half* Ks = smh;                   // [64 keys][HPAD d]
    __half* Vt = smh + 64 * HPAD;       // [64 d][HPAD keys]
    __half* Ps = smh + 2 * 64 * HPAD;   // [128 rows][HPAD] (Q staging, then P)

    const int qb = (int)gridDim.x - 1 - (int)blockIdx.x;   // longest-first
    const int bh = blockIdx.y;
    const int b   = bh >> 5;
    const int h   = bh & 31;
    const int kvh = h >> 2;
    const int tid = threadIdx.x;
    const int wid = tid >> 5;
    const int lane = tid & 31;
    const int g   = lane >> 2;
    const int tig = lane & 3;
    const int q0 = qb * 128;
    const int wr = wid * 32;

    // ---- stage Q tile as fp16, then pull k16 a-frags ----
#pragma unroll
    for (int t = 0; t < 16; t++) {
        int e = tid + t * 128;
        int r = e >> 4;
        int c = (e & 15) * 4;
        float4 v = *reinterpret_cast<const float4*>(
            Q + (size_t)(b * SEQ + q0 + r) * DM + h * HD + c);
        *reinterpret_cast<uint32_t*>(&Ps[r * HPAD + c])     = h2_u32(__floats2half2_rn(v.x, v.y));
        *reinterpret_cast<uint32_t*>(&Ps[r * HPAD + c + 2]) = h2_u32(__floats2half2_rn(v.z, v.w));
    }
    __syncthreads();
    uint32_t qa[2][4][4];
#pragma unroll
    for (int mt = 0; mt < 2; mt++) {
        const int r0 = wr + mt * 16 + g, r1 = r0 + 8;
#pragma unroll
        for (int st = 0; st < 4; st++) {
            const int kk = st * 16;
            qa[mt][st][0] = *reinterpret_cast<const uint32_t*>(&Ps[r0 * HPAD + kk + 2 * tig]);
            qa[mt][st][1] = *reinterpret_cast<const uint32_t*>(&Ps[r1 * HPAD + kk + 2 * tig]);
            qa[mt][st][2] = *reinterpret_cast<const uint32_t*>(&Ps[r0 * HPAD + kk + 2 * tig + 8]);
            qa[mt][st][3] = *reinterpret_cast<const uint32_t*>(&Ps[r1 * HPAD + kk + 2 * tig + 8]);
        }
    }
    __syncthreads();

    float oc[2][8][4];
#pragma unroll
    for (int mt = 0; mt < 2; mt++)
#pragma unroll
        for (int nt = 0; nt < 8; nt++)
#pragma unroll
            for (int r = 0; r < 4; r++) oc[mt][nt][r] = 0.f;
    float mrow[2][2] = {{-1e30f, -1e30f}, {-1e30f, -1e30f}};
    float lrow[2][2] = {{0.f, 0.f}, {0.f, 0.f}};

    const int nkt = 2 * qb + 2;
    for (int kt = 0; kt < nkt; kt++) {
        __syncthreads();   // prior PV reads of Vt done before overwrite
        // ---- load K [key][d] and V transposed [d][key], fp16 ----
#pragma unroll
        for (int t = 0; t < 8; t++) {
            int e = tid + t * 128;
            int r = e >> 4;              // key 0..63
            int c = (e & 15) * 4;        // d col
            size_t go = (size_t)(b * SEQ + kt * 64 + r) * (NKV * HD) + kvh * HD + c;
            float4 kv = *reinterpret_cast<const float4*>(K + go);
            *reinterpret_cast<uint32_t*>(&Ks[r * HPAD + c])     = h2_u32(__floats2half2_rn(kv.x, kv.y));
            *reinterpret_cast<uint32_t*>(&Ks[r * HPAD + c + 2]) = h2_u32(__floats2half2_rn(kv.z, kv.w));
            float4 vv = *reinterpret_cast<const float4*>(V + go);
            Vt[(c + 0) * HPAD + r] = __float2half_rn(vv.x);
            Vt[(c + 1) * HPAD + r] = __float2half_rn(vv.y);
            Vt[(c + 2) * HPAD + r] = __float2half_rn(vv.z);
            Vt[(c + 3) * HPAD + r] = __float2half_rn(vv.w);
        }
        __syncthreads();

        // ---- S = Q K^T (fp16 k16) ----
        float sc[2][8][4];
#pragma unroll
        for (int mt = 0; mt < 2; mt++)
#pragma unroll
            for (int nt = 0; nt < 8; nt++)
#pragma unroll
                for (int r = 0; r < 4; r++) sc[mt][nt][r] = 0.f;
#pragma unroll
        for (int st = 0; st < 4; st++) {
            const int kk = st * 16;
#pragma unroll
            for (int nt = 0; nt < 8; nt++) {
                const int key = nt * 8 + g;
                uint32_t b0 = *reinterpret_cast<const uint32_t*>(&Ks[key * HPAD + kk + 2 * tig]);
                uint32_t b1 = *reinterpret_cast<const uint32_t*>(&Ks[key * HPAD + kk + 2 * tig + 8]);
                MMA_F16(sc[0][nt], qa[0][st], b0, b1);
                MMA_F16(sc[1][nt], qa[1][st], b0, b1);
            }
        }

        // ---- scale + causal mask + online softmax (fp32) ----
        const bool tail = (kt >= 2 * qb);
#pragma unroll
        for (int mt = 0; mt < 2; mt++) {
            const int row0 = wr + mt * 16 + g, row1 = row0 + 8;
            const int gr0 = q0 + row0, gr1 = q0 + row1;
            float rm0 = -1e30f, rm1 = -1e30f;
#pragma unroll
            for (int nt = 0; nt < 8; nt++) {
                const int gc0 = kt * 64 + nt * 8 + tig * 2, gc1 = gc0 + 1;
                float s0 = sc[mt][nt][0] * 0.125f; if (tail && gc0 > gr0) s0 = -1e30f;
                float s1 = sc[mt][nt][1] * 0.125f; if (tail && gc1 > gr0) s1 = -1e30f;
                float s2 = sc[mt][nt][2] * 0.125f; if (tail && gc0 > gr1) s2 = -1e30f;
                float s3 = sc[mt][nt][3] * 0.125f; if (tail && gc1 > gr1) s3 = -1e30f;
                sc[mt][nt][0] = s0; sc[mt][nt][1] = s1;
                sc[mt][nt][2] = s2; sc[mt][nt][3] = s3;
                rm0 = fmaxf(rm0, fmaxf(s0, s1));
                rm1 = fmaxf(rm1, fmaxf(s2, s3));
            }
            rm0 = fmaxf(rm0, __shfl_xor_sync(0xFFFFFFFFu, rm0, 1));
            rm0 = fmaxf(rm0, __shfl_xor_sync(0xFFFFFFFFu, rm0, 2));
            rm1 = fmaxf(rm1, __shfl_xor_sync(0xFFFFFFFFu, rm1, 1));
            rm1 = fmaxf(rm1, __shfl_xor_sync(0xFFFFFFFFu, rm1, 2));

            const float mn0 = fmaxf(mrow[mt][0], rm0), mn1 = fmaxf(mrow[mt][1], rm1);
            const float corr0 = __expf(mrow[mt][0] - mn0), corr1 = __expf(mrow[mt][1] - mn1);
            mrow[mt][0] = mn0; mrow[mt][1] = mn1;

            float rs0 = 0.f, rs1 = 0.f;
#pragma unroll
            for (int nt = 0; nt < 8; nt++) {
                float p0 = __expf(sc[mt][nt][0] - mn0);
                float p1 = __expf(sc[mt][nt][1] - mn0);
                float p2 = __expf(sc[mt][nt][2] - mn1);
                float p3 = __expf(sc[mt][nt][3] - mn1);
                rs0 += p0 + p1; rs1 += p2 + p3;
                oc[mt][nt][0] *= corr0; oc[mt][nt][1] *= corr0;
                oc[mt][nt][2] *= corr1; oc[mt][nt][3] *= corr1;
                *reinterpret_cast<uint32_t*>(&Ps[row0 * HPAD + nt * 8 + tig * 2]) =
                    h2_u32(__floats2half2_rn(p0, p1));
                *reinterpret_cast<uint32_t*>(&Ps[row1 * HPAD + nt * 8 + tig * 2]) =
                    h2_u32(__floats2half2_rn(p2, p3));
            }
            rs0 += __shfl_xor_sync(0xFFFFFFFFu, rs0, 1);
            rs0 += __shfl_xor_sync(0xFFFFFFFFu, rs0, 2);
            rs1 += __shfl_xor_sync(0xFFFFFFFFu, rs1, 1);
            rs1 += __shfl_xor_sync(0xFFFFFFFFu, rs1, 2);
            lrow[mt][0] = lrow[mt][0] * corr0 + rs0;
            lrow[mt][1] = lrow[mt][1] * corr1 + rs1;
        }
        __syncwarp();

        // ---- O += P V (fp16 k16, V transposed) ----
#pragma unroll
        for (int st = 0; st < 4; st++) {
            const int kk = st * 16;
            uint32_t pa[2][4];
#pragma unroll
            for (int mt = 0; mt < 2; mt++) {
                const int row0 = wr + mt * 16 + g, row1 = row0 + 8;
                pa[mt][0] = *reinterpret_cast<const uint32_t*>(&Ps[row0 * HPAD + kk + 2 * tig]);
                pa[mt][1] = *reinterpret_cast<const uint32_t*>(&Ps[row1 * HPAD + kk + 2 * tig]);
                pa[mt][2] = *reinterpret_cast<const uint32_t*>(&Ps[row0 * HPAD + kk + 2 * tig + 8]);
                pa[mt][3] = *reinterpret_cast<const uint32_t*>(&Ps[row1 * HPAD + kk + 2 * tig + 8]);
            }
#pragma unroll
            for (int nt = 0; nt < 8; nt++) {
                const int dcol = nt * 8 + g;
                uint32_t b0 = *reinterpret_cast<const uint32_t*>(&Vt[dcol * HPAD + kk + 2 * tig]);
                uint32_t b1 = *reinterpret_cast<const uint32_t*>(&Vt[dcol * HPAD + kk + 2 * tig + 8]);
                MMA_F16(oc[0][nt], pa[0], b0, b1);
                MMA_F16(oc[1][nt], pa[1], b0, b1);
            }
        }
        __syncwarp();   // Ps reads done before next tile's stores
    }

    // ---- finalize: fp16 store (feeds O-projection) ----
#pragma unroll
    for (int mt = 0; mt < 2; mt++) {
        const float inv0 = 1.0f / lrow[mt][0], inv1 = 1.0f / lrow[mt][1];
        const size_t gr0 = (size_t)(b * SEQ + q0 + wr + mt * 16 + g);
#pragma unroll
        for (int nt = 0; nt < 8; nt++) {
            const int col = h * HD + nt * 8 + tig * 2;
            *reinterpret_cast<__half2*>(O + gr0 * DM + col) =
                __floats2half2_rn(oc[mt][nt][0] * inv0, oc[mt][nt][1] * inv0);
            *reinterpret_cast<__half2*>(O + (gr0 + 8) * DM + col) =
                __floats2half2_rn(oc[mt][nt][2] * inv1, oc[mt][nt][3] * inv1);
        }
    }
}

// ---------------- launch ----------------------------------------------------
extern "C" void kernel_launch(void* const* d_in, const int* in_sizes, int n_in,
                              void* d_out, int out_size) {
    const float* x  = (const float*)d_in[0];
    const float* Wq = (const float*)d_in[1];
    const float* Wk = (const float*)d_in[2];
    const float* Wv = (const float*)d_in[3];
    const float* Wo = (const float*)d_in[4];
    float* out = (float*)d_out;

    float *gq, *gk, *gv;
    __half *oh, *xh, *wqh, *wkh, *wvh, *woh;
    cudaGetSymbolAddress((void**)&gq, g_q);
    cudaGetSymbolAddress((void**)&gk, g_k);
    cudaGetSymbolAddress((void**)&gv, g_v);
    cudaGetSymbolAddress((void**)&oh, g_oh);
    cudaGetSymbolAddress((void**)&xh, g_xh);
    cudaGetSymbolAddress((void**)&wqh, g_wqh);
    cudaGetSymbolAddress((void**)&wkh, g_wkh);
    cudaGetSymbolAddress((void**)&wvh, g_wvh);
    cudaGetSymbolAddress((void**)&woh, g_woh);

    static bool attr_set = false;
    if (!attr_set) {
        cudaFuncSetAttribute(gemm_qkv, cudaFuncAttributeMaxDynamicSharedMemorySize, GEMM_SMEM);
        cudaFuncSetAttribute(gemm_single, cudaFuncAttributeMaxDynamicSharedMemorySize, GEMM_SMEM);
        cudaFuncSetAttribute(attn_mma, cudaFuncAttributeMaxDynamicSharedMemorySize, ATTN_SMEM);
        attr_set = true;
    }

    // pre-round all GEMM operands to fp16 (one launch)
    cvt_all_kernel<<<1184, 256>>>(
        (const float4*)x,  (uint2*)xh,  (int)((size_t)NT * DM / 4),
        (const float4*)Wq, (uint2*)wqh, (int)((size_t)DM * DM / 4),
        (const float4*)Wk, (uint2*)wkh, (int)((size_t)(NKV * HD) * DM / 4),
        (const float4*)Wv, (uint2*)wvh, (int)((size_t)(NKV * HD) * DM / 4),
        (const float4*)Wo, (uint2*)woh, (int)((size_t)DM * DM / 4));

    // Q + K + V projections, one launch
    gemm_qkv<<<768, 256, GEMM_SMEM>>>(xh, wqh, gq, wkh, gk, wvh, gv);

    // RoPE on q and k, one launch
    int tq = NT * NH * 32;
    int tk = NT * NKV * 32;
    rope_all<<<(tq + tk + 255) / 256, 256>>>(gq, gk, tq, tq + tk);

    // causal GQA attention (fp16 mma flash, 128 q-rows/block, longest-first)
    attn_mma<<<dim3(SEQ / 128, B_SZ * NH), 128, ATTN_SMEM>>>(gq, gk, gv, oh);

    // output projection into d_out
    gemm_single<<<dim3(DM / 128, NT / 128), 256, GEMM_SMEM>>>(oh, woh, out, DM, DM);
}

// round 16
// speedup vs baseline: 2.2533x; 1.0247x over previous
#include <cuda_runtime.h>
#include <cuda_fp16.h>
#include <cstdint>

#define B_SZ   2
#define SEQ    2048
#define DM     2048
#define NH     32
#define NKV    8
#define HD     64
#define NT     (B_SZ * SEQ)   // 4096 tokens

// ---------------- scratch (static device globals; no runtime allocation) ----
__device__ float  g_q[(size_t)NT * DM];           // fp32, feeds attention
__device__ float  g_k[(size_t)NT * NKV * HD];
__device__ float  g_v[(size_t)NT * NKV * HD];
__device__ __half g_oh[(size_t)NT * DM];          // attention out, fp16
__device__ __half g_xh[(size_t)NT * DM];          // fp16 operand copies
__device__ __half g_wqh[(size_t)DM * DM];
__device__ __half g_wkh[(size_t)(NKV * HD) * DM];
__device__ __half g_wvh[(size_t)(NKV * HD) * DM];
__device__ __half g_woh[(size_t)DM * DM];

#define MMA_F16(c, a, b0_, b1_) \
    asm volatile("mma.sync.aligned.m16n8k16.row.col.f32.f16.f16.f32 " \
                 "{%0,%1,%2,%3}, {%4,%5,%6,%7}, {%8,%9}, {%0,%1,%2,%3};" \
                 : "+f"((c)[0]), "+f"((c)[1]), "+f"((c)[2]), "+f"((c)[3]) \
                 : "r"((a)[0]), "r"((a)[1]), "r"((a)[2]), "r"((a)[3]), \
                   "r"(b0_), "r"(b1_))

__device__ __forceinline__ void cp16(uint32_t dst, const void* src) {
    asm volatile("cp.async.ca.shared.global [%0], [%1], 16;" :: "r"(dst), "l"(src));
}
__device__ __forceinline__ uint32_t smem_u32(const void* p) {
    uint32_t a;
    asm("{ .reg .u64 t; cvta.to.shared.u64 t, %1; cvt.u32.u64 %0, t; }" : "=r"(a) : "l"(p));
    return a;
}
__device__ __forceinline__ uint32_t h2_u32(__half2 h) {
    return *reinterpret_cast<uint32_t*>(&h);
}

// ---------------- fp16 pre-rounding pass (all 5 tensors, one launch) --------
__global__ void cvt_all_kernel(const float4* __restrict__ s0, uint2* __restrict__ d0, int n0,
                               const float4* __restrict__ s1, uint2* __restrict__ d1, int n1,
                               const float4* __restrict__ s2, uint2* __restrict__ d2, int n2,
                               const float4* __restrict__ s3, uint2* __restrict__ d3, int n3,
                               const float4* __restrict__ s4, uint2* __restrict__ d4, int n4) {
    const int stride = gridDim.x * blockDim.x;
    const int gid = blockIdx.x * blockDim.x + threadIdx.x;
#define CVT_SEG(S, D, N) \
    for (int i = gid; i < (N); i += stride) { \
        float4 v = (S)[i]; \
        __half2 h01 = __floats2half2_rn(v.x, v.y); \
        __half2 h23 = __floats2half2_rn(v.z, v.w); \
        uint2 u; \
        u.x = *reinterpret_cast<uint32_t*>(&h01); \
        u.y = *reinterpret_cast<uint32_t*>(&h23); \
        (D)[i] = u; \
    }
    CVT_SEG(s0, d0, n0)
    CVT_SEG(s1, d1, n1)
    CVT_SEG(s2, d2, n2)
    CVT_SEG(s3, d3, n3)
    CVT_SEG(s4, d4, n4)
#undef CVT_SEG
}

// ============ fp16 tensor GEMM: C[M,N] = A[M,K] * B[N,K]^T (R14) ============
#define BK 32
#define PADH 40
#define STAGE_H (128 * PADH)
#define STAGES 3
#define GEMM_SMEM (STAGES * 2 * STAGE_H * 2)      // 61440 B

__device__ __forceinline__ void gemm_tile(const __half* __restrict__ A,
                                          const __half* __restrict__ Bm,
                                          float* __restrict__ C,
                                          int N, int K, int m0, int n0,
                                          __half* smem) {
    const uint32_t sb = smem_u32(smem);
    const int tid = threadIdx.x;
    const int wid = tid >> 5;
    const int lane = tid & 31;
    const int g   = lane >> 2;
    const int tig = lane & 3;
    const int wm0 = (wid & 3) * 32;
    const int wn0 = (wid >> 2) * 64;

    float acc[2][8][4];
#pragma unroll
    for (int mt = 0; mt < 2; mt++)
#pragma unroll
        for (int nt = 0; nt < 8; nt++)
#pragma unroll
            for (int r = 0; r < 4; r++) acc[mt][nt][r] = 0.f;

    const int NITER = K / BK;

    auto issue_stage = [&](int kt, int s) {
        const int k0 = kt * BK;
        const uint32_t abase = sb + (uint32_t)(s * 2 * STAGE_H) * 2u;
        const uint32_t bbase = abase + (uint32_t)STAGE_H * 2u;
#pragma unroll
        for (int t = 0; t < 2; t++) {
            const int e = tid + t * 256;
            const int r = e >> 2;
            const int c = (e & 3) * 8;
            const uint32_t soff = (uint32_t)(r * PADH + c) * 2u;
            cp16(abase + soff, A  + (size_t)(m0 + r) * K + k0 + c);
            cp16(bbase + soff, Bm + (size_t)(n0 + r) * K + k0 + c);
        }
    };

#pragma unroll
    for (int s = 0; s < STAGES - 1; s++) {
        if (s < NITER) issue_stage(s, s);
        asm volatile("cp.async.commit_group;");
    }

    for (int i = 0; i < NITER; i++) {
        asm volatile("cp.async.wait_group %0;" :: "n"(STAGES - 2));
        __syncthreads();

        const __half* As = smem + (i % STAGES) * 2 * STAGE_H;
        const __half* Bs = As + STAGE_H;
#pragma unroll
        for (int step = 0; step < 2; step++) {
            const int kk = step * 16;
            uint32_t af[2][4], bf[8][2];
#pragma unroll
            for (int mt = 0; mt < 2; mt++) {
                const int am = wm0 + mt * 16 + g;
                af[mt][0] = *reinterpret_cast<const uint32_t*>(&As[(am)     * PADH + kk + 2 * tig]);
                af[mt][1] = *reinterpret_cast<const uint32_t*>(&As[(am + 8) * PADH + kk + 2 * tig]);
                af[mt][2] = *reinterpret_cast<const uint32_t*>(&As[(am)     * PADH + kk + 2 * tig + 8]);
                af[mt][3] = *reinterpret_cast<const uint32_t*>(&As[(am + 8) * PADH + kk + 2 * tig + 8]);
            }
#pragma unroll
            for (int nt = 0; nt < 8; nt++) {
                const int bn = wn0 + nt * 8 + g;
                bf[nt][0] = *reinterpret_cast<const uint32_t*>(&Bs[bn * PADH + kk + 2 * tig]);
                bf[nt][1] = *reinterpret_cast<const uint32_t*>(&Bs[bn * PADH + kk + 2 * tig + 8]);
            }
#pragma unroll
            for (int mt = 0; mt < 2; mt++)
#pragma unroll
                for (int nt = 0; nt < 8; nt++)
                    MMA_F16(acc[mt][nt], af[mt], bf[nt][0], bf[nt][1]);
        }

        if (i + STAGES - 1 < NITER) issue_stage(i + STAGES - 1, (i + STAGES - 1) % STAGES);
        asm volatile("cp.async.commit_group;");
    }

#pragma unroll
    for (int mt = 0; mt < 2; mt++) {
        const int row = m0 + wm0 + mt * 16 + g;
#pragma unroll
        for (int nt = 0; nt < 8; nt++) {
            const int col = n0 + wn0 + nt * 8 + tig * 2;
            const float* c = acc[mt][nt];
            *reinterpret_cast<float2*>(C + (size_t)row * N + col) = make_float2(c[0], c[1]);
            *reinterpret_cast<float2*>(C + (size_t)(row + 8) * N + col) = make_float2(c[2], c[3]);
        }
    }
}

__global__ void __launch_bounds__(256, 2)
gemm_qkv(const __half* __restrict__ A,
         const __half* __restrict__ Bq, float* __restrict__ Cq,
         const __half* __restrict__ Bk, float* __restrict__ Ck,
         const __half* __restrict__ Bv, float* __restrict__ Cv) {
    extern __shared__ __half smemh[];
    const int bid = blockIdx.x;
    if (bid < 512) {
        gemm_tile(A, Bq, Cq, DM, DM, (bid >> 4) * 128, (bid & 15) * 128, smemh);
    } else if (bid < 640) {
        const int t = bid - 512;
        gemm_tile(A, Bk, Ck, NKV * HD, DM, (t >> 2) * 128, (t & 3) * 128, smemh);
    } else {
        const int t = bid - 640;
        gemm_tile(A, Bv, Cv, NKV * HD, DM, (t >> 2) * 128, (t & 3) * 128, smemh);
    }
}

__global__ void __launch_bounds__(256, 2)
gemm_single(const __half* __restrict__ A, const __half* __restrict__ Bm,
            float* __restrict__ C, int N, int K) {
    extern __shared__ __half smemh[];
    gemm_tile(A, Bm, C, N, K, blockIdx.y * 128, blockIdx.x * 128, smemh);
}

// ---------------- RoPE (q and k in one launch) ------------------------------
__global__ void rope_all(float* __restrict__ q, float* __restrict__ k,
                         int tq, int total) {
    int idx = blockIdx.x * blockDim.x + threadIdx.x;
    if (idx >= total) return;
    float* buf;
    int nheads;
    if (idx < tq) { buf = q; nheads = NH; }
    else          { idx -= tq; buf = k; nheads = NKV; }
    int d   = idx & 31;
    int h   = (idx >> 5) % nheads;
    int row = idx / (32 * nheads);
    int s   = row & (SEQ - 1);
    float inv = expf(-(float)d * (9.210340371976184f / 32.0f));
    float ang = (float)s * inv;
    float c  = cosf(ang);
    float si = sinf(ang);
    float* p = buf + (size_t)row * (nheads * HD) + h * HD;
    float x1 = p[d];
    float x2 = p[d + 32];
    p[d]      = x1 * c - x2 * si;
    p[d + 32] = x2 * c + x1 * si;
}

// ======== causal GQA flash attention, fp16 mma, register-resident P =========
// 128 q-rows/block, 4 warps, 32 q-rows/warp. K [key][d], V transposed [d][key].
// QK c-frags repacked in-registers as PV a-frags (no P smem round trip).
#define HPAD 72
#define ATTN_SMEM ((2 * 64 * HPAD + 128 * HPAD) * 2)   // 36864 B (Q staging reuse)

__global__ void __launch_bounds__(128)
attn_mma(const float* __restrict__ Q, const float* __restrict__ K,
         const float* __restrict__ V, __half* __restrict__ O) {
    extern __shared__ __half smh[];
    __half* Ks = smh;                   // [64 keys][HPAD d]
    __half* Vt = smh + 64 * HPAD;       // [64 d][HPAD keys]
    __half* Qs = smh + 2 * 64 * HPAD;   // [128 rows][HPAD] (Q staging only)

    const int qb = (int)gridDim.x - 1 - (int)blockIdx.x;   // longest-first
    const int bh = blockIdx.y;
    const int b   = bh >> 5;
    const int h   = bh & 31;
    const int kvh = h >> 2;
    const int tid = threadIdx.x;
    const int wid = tid >> 5;
    const int lane = tid & 31;
    const int g   = lane >> 2;
    const int tig = lane & 3;
    const int q0 = qb * 128;
    const int wr = wid * 32;

    // ---- stage Q tile as fp16, then pull k16 a-frags ----
#pragma unroll
    for (int t = 0; t < 16; t++) {
        int e = tid + t * 128;
        int r = e >> 4;
        int c = (e & 15) * 4;
        float4 v = *reinterpret_cast<const float4*>(
            Q + (size_t)(b * SEQ + q0 + r) * DM + h * HD + c);
        *reinterpret_cast<uint32_t*>(&Qs[r * HPAD + c])     = h2_u32(__floats2half2_rn(v.x, v.y));
        *reinterpret_cast<uint32_t*>(&Qs[r * HPAD + c + 2]) = h2_u32(__floats2half2_rn(v.z, v.w));
    }
    __syncthreads();
    uint32_t qa[2][4][4];
#pragma unroll
    for (int mt = 0; mt < 2; mt++) {
        const int r0 = wr + mt * 16 + g, r1 = r0 + 8;
#pragma unroll
        for (int st = 0; st < 4; st++) {
            const int kk = st * 16;
            qa[mt][st][0] = *reinterpret_cast<const uint32_t*>(&Qs[r0 * HPAD + kk + 2 * tig]);
            qa[mt][st][1] = *reinterpret_cast<const uint32_t*>(&Qs[r1 * HPAD + kk + 2 * tig]);
            qa[mt][st][2] = *reinterpret_cast<const uint32_t*>(&Qs[r0 * HPAD + kk + 2 * tig + 8]);
            qa[mt][st][3] = *reinterpret_cast<const uint32_t*>(&Qs[r1 * HPAD + kk + 2 * tig + 8]);
        }
    }
    __syncthreads();

    float oc[2][8][4];
#pragma unroll
    for (int mt = 0; mt < 2; mt++)
#pragma unroll
        for (int nt = 0; nt < 8; nt++)
#pragma unroll
            for (int r = 0; r < 4; r++) oc[mt][nt][r] = 0.f;
    float mrow[2][2] = {{-1e30f, -1e30f}, {-1e30f, -1e30f}};
    float lrow[2][2] = {{0.f, 0.f}, {0.f, 0.f}};

    const int nkt = 2 * qb + 2;
    for (int kt = 0; kt < nkt; kt++) {
        __syncthreads();   // prior PV reads of Ks/Vt done before overwrite
        // ---- load K [key][d] and V transposed [d][key], fp16 ----
#pragma unroll
        for (int t = 0; t < 8; t++) {
            int e = tid + t * 128;
            int r = e >> 4;              // key 0..63
            int c = (e & 15) * 4;        // d col
            size_t go = (size_t)(b * SEQ + kt * 64 + r) * (NKV * HD) + kvh * HD + c;
            float4 kv = *reinterpret_cast<const float4*>(K + go);
            *reinterpret_cast<uint32_t*>(&Ks[r * HPAD + c])     = h2_u32(__floats2half2_rn(kv.x, kv.y));
            *reinterpret_cast<uint32_t*>(&Ks[r * HPAD + c + 2]) = h2_u32(__floats2half2_rn(kv.z, kv.w));
            float4 vv = *reinterpret_cast<const float4*>(V + go);
            Vt[(c + 0) * HPAD + r] = __float2half_rn(vv.x);
            Vt[(c + 1) * HPAD + r] = __float2half_rn(vv.y);
            Vt[(c + 2) * HPAD + r] = __float2half_rn(vv.z);
            Vt[(c + 3) * HPAD + r] = __float2half_rn(vv.w);
        }
        __syncthreads();

        // ---- S = Q K^T (fp16 k16) ----
        float sc[2][8][4];
#pragma unroll
        for (int mt = 0; mt < 2; mt++)
#pragma unroll
            for (int nt = 0; nt < 8; nt++)
#pragma unroll
                for (int r = 0; r < 4; r++) sc[mt][nt][r] = 0.f;
#pragma unroll
        for (int st = 0; st < 4; st++) {
            const int kk = st * 16;
#pragma unroll
            for (int nt = 0; nt < 8; nt++) {
                const int key = nt * 8 + g;
                uint32_t b0 = *reinterpret_cast<const uint32_t*>(&Ks[key * HPAD + kk + 2 * tig]);
                uint32_t b1 = *reinterpret_cast<const uint32_t*>(&Ks[key * HPAD + kk + 2 * tig + 8]);
                MMA_F16(sc[0][nt], qa[0][st], b0, b1);
                MMA_F16(sc[1][nt], qa[1][st], b0, b1);
            }
        }

        // ---- scale + mask + online softmax; pack P c-frags as PV a-frags ----
        const bool tail = (kt >= 2 * qb);
        uint32_t pp[2][4][4];
#pragma unroll
        for (int mt = 0; mt < 2; mt++) {
            const int row0 = wr + mt * 16 + g, row1 = row0 + 8;
            const int gr0 = q0 + row0, gr1 = q0 + row1;
            float rm0 = -1e30f, rm1 = -1e30f;
#pragma unroll
            for (int nt = 0; nt < 8; nt++) {
                const int gc0 = kt * 64 + nt * 8 + tig * 2, gc1 = gc0 + 1;
                float s0 = sc[mt][nt][0] * 0.125f; if (tail && gc0 > gr0) s0 = -1e30f;
                float s1 = sc[mt][nt][1] * 0.125f; if (tail && gc1 > gr0) s1 = -1e30f;
                float s2 = sc[mt][nt][2] * 0.125f; if (tail && gc0 > gr1) s2 = -1e30f;
                float s3 = sc[mt][nt][3] * 0.125f; if (tail && gc1 > gr1) s3 = -1e30f;
                sc[mt][nt][0] = s0; sc[mt][nt][1] = s1;
                sc[mt][nt][2] = s2; sc[mt][nt][3] = s3;
                rm0 = fmaxf(rm0, fmaxf(s0, s1));
                rm1 = fmaxf(rm1, fmaxf(s2, s3));
            }
            rm0 = fmaxf(rm0, __shfl_xor_sync(0xFFFFFFFFu, rm0, 1));
            rm0 = fmaxf(rm0, __shfl_xor_sync(0xFFFFFFFFu, rm0, 2));
            rm1 = fmaxf(rm1, __shfl_xor_sync(0xFFFFFFFFu, rm1, 1));
            rm1 = fmaxf(rm1, __shfl_xor_sync(0xFFFFFFFFu, rm1, 2));

            const float mn0 = fmaxf(mrow[mt][0], rm0), mn1 = fmaxf(mrow[mt][1], rm1);
            const float corr0 = __expf(mrow[mt][0] - mn0), corr1 = __expf(mrow[mt][1] - mn1);
            mrow[mt][0] = mn0; mrow[mt][1] = mn1;

            float rs0 = 0.f, rs1 = 0.f;
#pragma unroll
            for (int nt = 0; nt < 8; nt++) {
                float p0 = __expf(sc[mt][nt][0] - mn0);
                float p1 = __expf(sc[mt][nt][1] - mn0);
                float p2 = __expf(sc[mt][nt][2] - mn1);
                float p3 = __expf(sc[mt][nt][3] - mn1);
                rs0 += p0 + p1; rs1 += p2 + p3;
                oc[mt][nt][0] *= corr0; oc[mt][nt][1] *= corr0;
                oc[mt][nt][2] *= corr1; oc[mt][nt][3] *= corr1;
                // c-frag -> a-frag repack (nt=2st -> regs 0,1; nt=2st+1 -> regs 2,3)
                const int st = nt >> 1;
                if ((nt & 1) == 0) {
                    pp[mt][st][0] = h2_u32(__floats2half2_rn(p0, p1));
                    pp[mt][st][1] = h2_u32(__floats2half2_rn(p2, p3));
                } else {
                    pp[mt][st][2] = h2_u32(__floats2half2_rn(p0, p1));
                    pp[mt][st][3] = h2_u32(__floats2half2_rn(p2, p3));
                }
            }
            rs0 += __shfl_xor_sync(0xFFFFFFFFu, rs0, 1);
            rs0 += __shfl_xor_sync(0xFFFFFFFFu, rs0, 2);
            rs1 += __shfl_xor_sync(0xFFFFFFFFu, rs1, 1);
            rs1 += __shfl_xor_sync(0xFFFFFFFFu, rs1, 2);
            lrow[mt][0] = lrow[mt][0] * corr0 + rs0;
            lrow[mt][1] = lrow[mt][1] * corr1 + rs1;
        }

        // ---- O += P V (P in registers, V transposed in smem) ----
#pragma unroll
        for (int st = 0; st < 4; st++) {
            const int kk = st * 16;
#pragma unroll
            for (int nt = 0; nt < 8; nt++) {
                const int dcol = nt * 8 + g;
                uint32_t b0 = *reinterpret_cast<const uint32_t*>(&Vt[dcol * HPAD + kk + 2 * tig]);
                uint32_t b1 = *reinterpret_cast<const uint32_t*>(&Vt[dcol * HPAD + kk + 2 * tig + 8]);
                MMA_F16(oc[0][nt], pp[0][st], b0, b1);
                MMA_F16(oc[1][nt], pp[1][st], b0, b1);
            }
        }
    }

    // ---- finalize: fp16 store (feeds O-projection) ----
#pragma unroll
    for (int mt = 0; mt < 2; mt++) {
        const float inv0 = 1.0f / lrow[mt][0], inv1 = 1.0f / lrow[mt][1];
        const size_t gr0 = (size_t)(b * SEQ + q0 + wr + mt * 16 + g);
#pragma unroll
        for (int nt = 0; nt < 8; nt++) {
            const int col = h * HD + nt * 8 + tig * 2;
            *reinterpret_cast<__half2*>(O + gr0 * DM + col) =
                __floats2half2_rn(oc[mt][nt][0] * inv0, oc[mt][nt][1] * inv0);
            *reinterpret_cast<__half2*>(O + (gr0 + 8) * DM + col) =
                __floats2half2_rn(oc[mt][nt][2] * inv1, oc[mt][nt][3] * inv1);
        }
    }
}

// ---------------- launch ----------------------------------------------------
extern "C" void kernel_launch(void* const* d_in, const int* in_sizes, int n_in,
                              void* d_out, int out_size) {
    const float* x  = (const float*)d_in[0];
    const float* Wq = (const float*)d_in[1];
    const float* Wk = (const float*)d_in[2];
    const float* Wv = (const float*)d_in[3];
    const float* Wo = (const float*)d_in[4];
    float* out = (float*)d_out;

    float *gq, *gk, *gv;
    __half *oh, *xh, *wqh, *wkh, *wvh, *woh;
    cudaGetSymbolAddress((void**)&gq, g_q);
    cudaGetSymbolAddress((void**)&gk, g_k);
    cudaGetSymbolAddress((void**)&gv, g_v);
    cudaGetSymbolAddress((void**)&oh, g_oh);
    cudaGetSymbolAddress((void**)&xh, g_xh);
    cudaGetSymbolAddress((void**)&wqh, g_wqh);
    cudaGetSymbolAddress((void**)&wkh, g_wkh);
    cudaGetSymbolAddress((void**)&wvh, g_wvh);
    cudaGetSymbolAddress((void**)&woh, g_woh);

    static bool attr_set = false;
    if (!attr_set) {
        cudaFuncSetAttribute(gemm_qkv, cudaFuncAttributeMaxDynamicSharedMemorySize, GEMM_SMEM);
        cudaFuncSetAttribute(gemm_single, cudaFuncAttributeMaxDynamicSharedMemorySize, GEMM_SMEM);
        cudaFuncSetAttribute(attn_mma, cudaFuncAttributeMaxDynamicSharedMemorySize, ATTN_SMEM);
        attr_set = true;
    }

    // pre-round all GEMM operands to fp16 (one launch)
    cvt_all_kernel<<<1184, 256>>>(
        (const float4*)x,  (uint2*)xh,  (int)((size_t)NT * DM / 4),
        (const float4*)Wq, (uint2*)wqh, (int)((size_t)DM * DM / 4),
        (const float4*)Wk, (uint2*)wkh, (int)((size_t)(NKV * HD) * DM / 4),
        (const float4*)Wv, (uint2*)wvh, (int)((size_t)(NKV * HD) * DM / 4),
        (const float4*)Wo, (uint2*)woh, (int)((size_t)DM * DM / 4));

    // Q + K + V projections, one launch
    gemm_qkv<<<768, 256, GEMM_SMEM>>>(xh, wqh, gq, wkh, gk, wvh, gv);

    // RoPE on q and k, one launch
    int tq = NT * NH * 32;
    int tk = NT * NKV * 32;
    rope_all<<<(tq + tk + 255) / 256, 256>>>(gq, gk, tq, tq + tk);

    // causal GQA attention (fp16 mma flash, register-resident P)
    attn_mma<<<dim3(SEQ / 128, B_SZ * NH), 128, ATTN_SMEM>>>(gq, gk, gv, oh);

    // output projection into d_out
    gemm_single<<<dim3(DM / 128, NT / 128), 256, GEMM_SMEM>>>(oh, woh, out, DM, DM);
}

// round 17
// speedup vs baseline: 2.4160x; 1.0722x over previous
#include <cuda_runtime.h>
#include <cuda_fp16.h>
#include <cstdint>

#define B_SZ   2
#define SEQ    2048
#define DM     2048
#define NH     32
#define NKV    8
#define HD     64
#define NT     (B_SZ * SEQ)   // 4096 tokens

// ---------------- scratch (static device globals; no runtime allocation) ----
__device__ float  g_q[(size_t)NT * DM];           // fp32, feeds attention
__device__ float  g_k[(size_t)NT * NKV * HD];
__device__ float  g_v[(size_t)NT * NKV * HD];
__device__ __half g_oh[(size_t)NT * DM];          // attention out, fp16
__device__ __half g_xh[(size_t)NT * DM];          // fp16 operand copies
__device__ __half g_wqh[(size_t)DM * DM];
__device__ __half g_wkh[(size_t)(NKV * HD) * DM];
__device__ __half g_wvh[(size_t)(NKV * HD) * DM];
__device__ __half g_woh[(size_t)DM * DM];

#define MMA_F16(c, a, b0_, b1_) \
    asm volatile("mma.sync.aligned.m16n8k16.row.col.f32.f16.f16.f32 " \
                 "{%0,%1,%2,%3}, {%4,%5,%6,%7}, {%8,%9}, {%0,%1,%2,%3};" \
                 : "+f"((c)[0]), "+f"((c)[1]), "+f"((c)[2]), "+f"((c)[3]) \
                 : "r"((a)[0]), "r"((a)[1]), "r"((a)[2]), "r"((a)[3]), \
                   "r"(b0_), "r"(b1_))

__device__ __forceinline__ void cp16(uint32_t dst, const void* src) {
    asm volatile("cp.async.ca.shared.global [%0], [%1], 16;" :: "r"(dst), "l"(src));
}
__device__ __forceinline__ uint32_t smem_u32(const void* p) {
    uint32_t a;
    asm("{ .reg .u64 t; cvta.to.shared.u64 t, %1; cvt.u32.u64 %0, t; }" : "=r"(a) : "l"(p));
    return a;
}
__device__ __forceinline__ uint32_t h2_u32(__half2 h) {
    return *reinterpret_cast<uint32_t*>(&h);
}

// ---------------- fp16 pre-rounding pass (all 5 tensors, one launch) --------
__global__ void cvt_all_kernel(const float4* __restrict__ s0, uint2* __restrict__ d0, int n0,
                               const float4* __restrict__ s1, uint2* __restrict__ d1, int n1,
                               const float4* __restrict__ s2, uint2* __restrict__ d2, int n2,
                               const float4* __restrict__ s3, uint2* __restrict__ d3, int n3,
                               const float4* __restrict__ s4, uint2* __restrict__ d4, int n4) {
    const int stride = gridDim.x * blockDim.x;
    const int gid = blockIdx.x * blockDim.x + threadIdx.x;
#define CVT_SEG(S, D, N) \
    for (int i = gid; i < (N); i += stride) { \
        float4 v = (S)[i]; \
        __half2 h01 = __floats2half2_rn(v.x, v.y); \
        __half2 h23 = __floats2half2_rn(v.z, v.w); \
        uint2 u; \
        u.x = *reinterpret_cast<uint32_t*>(&h01); \
        u.y = *reinterpret_cast<uint32_t*>(&h23); \
        (D)[i] = u; \
    }
    CVT_SEG(s0, d0, n0)
    CVT_SEG(s1, d1, n1)
    CVT_SEG(s2, d2, n2)
    CVT_SEG(s3, d3, n3)
    CVT_SEG(s4, d4, n4)
#undef CVT_SEG
}

// ============ fp16 tensor GEMM: C[M,N] = A[M,K] * B[N,K]^T (R14) ============
#define BK 32
#define PADH 40
#define STAGE_H (128 * PADH)
#define STAGES 3
#define GEMM_SMEM (STAGES * 2 * STAGE_H * 2)      // 61440 B

__device__ __forceinline__ void gemm_tile(const __half* __restrict__ A,
                                          const __half* __restrict__ Bm,
                                          float* __restrict__ C,
                                          int N, int K, int m0, int n0,
                                          __half* smem) {
    const uint32_t sb = smem_u32(smem);
    const int tid = threadIdx.x;
    const int wid = tid >> 5;
    const int lane = tid & 31;
    const int g   = lane >> 2;
    const int tig = lane & 3;
    const int wm0 = (wid & 3) * 32;
    const int wn0 = (wid >> 2) * 64;

    float acc[2][8][4];
#pragma unroll
    for (int mt = 0; mt < 2; mt++)
#pragma unroll
        for (int nt = 0; nt < 8; nt++)
#pragma unroll
            for (int r = 0; r < 4; r++) acc[mt][nt][r] = 0.f;

    const int NITER = K / BK;

    auto issue_stage = [&](int kt, int s) {
        const int k0 = kt * BK;
        const uint32_t abase = sb + (uint32_t)(s * 2 * STAGE_H) * 2u;
        const uint32_t bbase = abase + (uint32_t)STAGE_H * 2u;
#pragma unroll
        for (int t = 0; t < 2; t++) {
            const int e = tid + t * 256;
            const int r = e >> 2;
            const int c = (e & 3) * 8;
            const uint32_t soff = (uint32_t)(r * PADH + c) * 2u;
            cp16(abase + soff, A  + (size_t)(m0 + r) * K + k0 + c);
            cp16(bbase + soff, Bm + (size_t)(n0 + r) * K + k0 + c);
        }
    };

#pragma unroll
    for (int s = 0; s < STAGES - 1; s++) {
        if (s < NITER) issue_stage(s, s);
        asm volatile("cp.async.commit_group;");
    }

    for (int i = 0; i < NITER; i++) {
        asm volatile("cp.async.wait_group %0;" :: "n"(STAGES - 2));
        __syncthreads();

        const __half* As = smem + (i % STAGES) * 2 * STAGE_H;
        const __half* Bs = As + STAGE_H;
#pragma unroll
        for (int step = 0; step < 2; step++) {
            const int kk = step * 16;
            uint32_t af[2][4], bf[8][2];
#pragma unroll
            for (int mt = 0; mt < 2; mt++) {
                const int am = wm0 + mt * 16 + g;
                af[mt][0] = *reinterpret_cast<const uint32_t*>(&As[(am)     * PADH + kk + 2 * tig]);
                af[mt][1] = *reinterpret_cast<const uint32_t*>(&As[(am + 8) * PADH + kk + 2 * tig]);
                af[mt][2] = *reinterpret_cast<const uint32_t*>(&As[(am)     * PADH + kk + 2 * tig + 8]);
                af[mt][3] = *reinterpret_cast<const uint32_t*>(&As[(am + 8) * PADH + kk + 2 * tig + 8]);
            }
#pragma unroll
            for (int nt = 0; nt < 8; nt++) {
                const int bn = wn0 + nt * 8 + g;
                bf[nt][0] = *reinterpret_cast<const uint32_t*>(&Bs[bn * PADH + kk + 2 * tig]);
                bf[nt][1] = *reinterpret_cast<const uint32_t*>(&Bs[bn * PADH + kk + 2 * tig + 8]);
            }
#pragma unroll
            for (int mt = 0; mt < 2; mt++)
#pragma unroll
                for (int nt = 0; nt < 8; nt++)
                    MMA_F16(acc[mt][nt], af[mt], bf[nt][0], bf[nt][1]);
        }

        if (i + STAGES - 1 < NITER) issue_stage(i + STAGES - 1, (i + STAGES - 1) % STAGES);
        asm volatile("cp.async.commit_group;");
    }

#pragma unroll
    for (int mt = 0; mt < 2; mt++) {
        const int row = m0 + wm0 + mt * 16 + g;
#pragma unroll
        for (int nt = 0; nt < 8; nt++) {
            const int col = n0 + wn0 + nt * 8 + tig * 2;
            const float* c = acc[mt][nt];
            *reinterpret_cast<float2*>(C + (size_t)row * N + col) = make_float2(c[0], c[1]);
            *reinterpret_cast<float2*>(C + (size_t)(row + 8) * N + col) = make_float2(c[2], c[3]);
        }
    }
}

__global__ void __launch_bounds__(256, 2)
gemm_qkv(const __half* __restrict__ A,
         const __half* __restrict__ Bq, float* __restrict__ Cq,
         const __half* __restrict__ Bk, float* __restrict__ Ck,
         const __half* __restrict__ Bv, float* __restrict__ Cv) {
    extern __shared__ __half smemh[];
    const int bid = blockIdx.x;
    if (bid < 512) {
        gemm_tile(A, Bq, Cq, DM, DM, (bid >> 4) * 128, (bid & 15) * 128, smemh);
    } else if (bid < 640) {
        const int t = bid - 512;
        gemm_tile(A, Bk, Ck, NKV * HD, DM, (t >> 2) * 128, (t & 3) * 128, smemh);
    } else {
        const int t = bid - 640;
        gemm_tile(A, Bv, Cv, NKV * HD, DM, (t >> 2) * 128, (t & 3) * 128, smemh);
    }
}

__global__ void __launch_bounds__(256, 2)
gemm_single(const __half* __restrict__ A, const __half* __restrict__ Bm,
            float* __restrict__ C, int N, int K) {
    extern __shared__ __half smemh[];
    gemm_tile(A, Bm, C, N, K, blockIdx.y * 128, blockIdx.x * 128, smemh);
}

// ---------------- RoPE (q and k in one launch) ------------------------------
__global__ void rope_all(float* __restrict__ q, float* __restrict__ k,
                         int tq, int total) {
    int idx = blockIdx.x * blockDim.x + threadIdx.x;
    if (idx >= total) return;
    float* buf;
    int nheads;
    if (idx < tq) { buf = q; nheads = NH; }
    else          { idx -= tq; buf = k; nheads = NKV; }
    int d   = idx & 31;
    int h   = (idx >> 5) % nheads;
    int row = idx / (32 * nheads);
    int s   = row & (SEQ - 1);
    float inv = expf(-(float)d * (9.210340371976184f / 32.0f));
    float ang = (float)s * inv;
    float c  = cosf(ang);
    float si = sinf(ang);
    float* p = buf + (size_t)row * (nheads * HD) + h * HD;
    float x1 = p[d];
    float x2 = p[d + 32];
    p[d]      = x1 * c - x2 * si;
    p[d + 32] = x2 * c + x1 * si;
}

// ======== causal GQA flash attention, fp16 mma, register-resident P =========
// 128 q-rows/block, 4 warps, 32 q-rows/warp. K [key][d], V transposed [d][key]
// (conflict-reduced d-interleaved transpose). Q pre-scaled by 1/8 (exact).
#define HPAD 72
#define ATTN_SMEM ((2 * 64 * HPAD + 128 * HPAD) * 2)   // 36864 B

__global__ void __launch_bounds__(128)
attn_mma(const float* __restrict__ Q, const float* __restrict__ K,
         const float* __restrict__ V, __half* __restrict__ O) {
    extern __shared__ __half smh[];
    __half* Ks = smh;                   // [64 keys][HPAD d]
    __half* Vt = smh + 64 * HPAD;       // [64 d][HPAD keys]
    __half* Qs = smh + 2 * 64 * HPAD;   // [128 rows][HPAD] (Q staging only)

    const int qb = (int)gridDim.x - 1 - (int)blockIdx.x;   // longest-first
    const int bh = blockIdx.y;
    const int b   = bh >> 5;
    const int h   = bh & 31;
    const int kvh = h >> 2;
    const int tid = threadIdx.x;
    const int wid = tid >> 5;
    const int lane = tid & 31;
    const int g   = lane >> 2;
    const int tig = lane & 3;
    const int q0 = qb * 128;
    const int wr = wid * 32;

    // ---- stage Q tile as fp16 (pre-scaled by 1/8 — exact), pull a-frags ----
#pragma unroll
    for (int t = 0; t < 16; t++) {
        int e = tid + t * 128;
        int r = e >> 4;
        int c = (e & 15) * 4;
        float4 v = *reinterpret_cast<const float4*>(
            Q + (size_t)(b * SEQ + q0 + r) * DM + h * HD + c);
        *reinterpret_cast<uint32_t*>(&Qs[r * HPAD + c]) =
            h2_u32(__floats2half2_rn(v.x * 0.125f, v.y * 0.125f));
        *reinterpret_cast<uint32_t*>(&Qs[r * HPAD + c + 2]) =
            h2_u32(__floats2half2_rn(v.z * 0.125f, v.w * 0.125f));
    }
    __syncthreads();
    uint32_t qa[2][4][4];
#pragma unroll
    for (int mt = 0; mt < 2; mt++) {
        const int r0 = wr + mt * 16 + g, r1 = r0 + 8;
#pragma unroll
        for (int st = 0; st < 4; st++) {
            const int kk = st * 16;
            qa[mt][st][0] = *reinterpret_cast<const uint32_t*>(&Qs[r0 * HPAD + kk + 2 * tig]);
            qa[mt][st][1] = *reinterpret_cast<const uint32_t*>(&Qs[r1 * HPAD + kk + 2 * tig]);
            qa[mt][st][2] = *reinterpret_cast<const uint32_t*>(&Qs[r0 * HPAD + kk + 2 * tig + 8]);
            qa[mt][st][3] = *reinterpret_cast<const uint32_t*>(&Qs[r1 * HPAD + kk + 2 * tig + 8]);
        }
    }
    __syncthreads();

    float oc[2][8][4];
#pragma unroll
    for (int mt = 0; mt < 2; mt++)
#pragma unroll
        for (int nt = 0; nt < 8; nt++)
#pragma unroll
            for (int r = 0; r < 4; r++) oc[mt][nt][r] = 0.f;
    float mrow[2][2] = {{-1e30f, -1e30f}, {-1e30f, -1e30f}};
    float lrow[2][2] = {{0.f, 0.f}, {0.f, 0.f}};

    const int nkt = 2 * qb + 2;
    for (int kt = 0; kt < nkt; kt++) {
        __syncthreads();   // prior MMA reads of Ks/Vt done before overwrite
        const size_t tok0 = (size_t)(b * SEQ + kt * 64);
        // ---- K [key][d]: float4-coalesced, fp16 ----
#pragma unroll
        for (int t = 0; t < 8; t++) {
            int e = tid + t * 128;
            int r = e >> 4;              // key 0..63
            int c = (e & 15) * 4;        // d col
            float4 kv = *reinterpret_cast<const float4*>(
                K + (tok0 + r) * (NKV * HD) + kvh * HD + c);
            *reinterpret_cast<uint32_t*>(&Ks[r * HPAD + c])     = h2_u32(__floats2half2_rn(kv.x, kv.y));
            *reinterpret_cast<uint32_t*>(&Ks[r * HPAD + c + 2]) = h2_u32(__floats2half2_rn(kv.z, kv.w));
        }
        // ---- V transposed [d][key]: d-interleaved (2-way instead of 8-way) ----
#pragma unroll
        for (int t = 0; t < 8; t++) {
            int e = tid + t * 128;
            int r = e >> 4;              // key 0..63
            int j = e & 15;              // d base
            const float* vp = V + (tok0 + r) * (NKV * HD) + kvh * HD + j;
#pragma unroll
            for (int i = 0; i < 4; i++) {
                Vt[(j + 16 * i) * HPAD + r] = __float2half_rn(vp[16 * i]);
            }
        }
        __syncthreads();

        // ---- S = (Q/8) K^T (fp16 k16) ----
        float sc[2][8][4];
#pragma unroll
        for (int mt = 0; mt < 2; mt++)
#pragma unroll
            for (int nt = 0; nt < 8; nt++)
#pragma unroll
                for (int r = 0; r < 4; r++) sc[mt][nt][r] = 0.f;
#pragma unroll
        for (int st = 0; st < 4; st++) {
            const int kk = st * 16;
#pragma unroll
            for (int nt = 0; nt < 8; nt++) {
                const int key = nt * 8 + g;
                uint32_t b0 = *reinterpret_cast<const uint32_t*>(&Ks[key * HPAD + kk + 2 * tig]);
                uint32_t b1 = *reinterpret_cast<const uint32_t*>(&Ks[key * HPAD + kk + 2 * tig + 8]);
                MMA_F16(sc[0][nt], qa[0][st], b0, b1);
                MMA_F16(sc[1][nt], qa[1][st], b0, b1);
            }
        }

        // ---- mask + online softmax; pack P c-frags as PV a-frags ----
        const bool tail = (kt >= 2 * qb);
        uint32_t pp[2][4][4];
#pragma unroll
        for (int mt = 0; mt < 2; mt++) {
            const int row0 = wr + mt * 16 + g, row1 = row0 + 8;
            const int gr0 = q0 + row0, gr1 = q0 + row1;
            float rm0 = -1e30f, rm1 = -1e30f;
#pragma unroll
            for (int nt = 0; nt < 8; nt++) {
                const int gc0 = kt * 64 + nt * 8 + tig * 2, gc1 = gc0 + 1;
                float s0 = sc[mt][nt][0]; if (tail && gc0 > gr0) s0 = -1e30f;
                float s1 = sc[mt][nt][1]; if (tail && gc1 > gr0) s1 = -1e30f;
                float s2 = sc[mt][nt][2]; if (tail && gc0 > gr1) s2 = -1e30f;
                float s3 = sc[mt][nt][3]; if (tail && gc1 > gr1) s3 = -1e30f;
                sc[mt][nt][0] = s0; sc[mt][nt][1] = s1;
                sc[mt][nt][2] = s2; sc[mt][nt][3] = s3;
                rm0 = fmaxf(rm0, fmaxf(s0, s1));
                rm1 = fmaxf(rm1, fmaxf(s2, s3));
            }
            rm0 = fmaxf(rm0, __shfl_xor_sync(0xFFFFFFFFu, rm0, 1));
            rm0 = fmaxf(rm0, __shfl_xor_sync(0xFFFFFFFFu, rm0, 2));
            rm1 = fmaxf(rm1, __shfl_xor_sync(0xFFFFFFFFu, rm1, 1));
            rm1 = fmaxf(rm1, __shfl_xor_sync(0xFFFFFFFFu, rm1, 2));

            const float mn0 = fmaxf(mrow[mt][0], rm0), mn1 = fmaxf(mrow[mt][1], rm1);
            const float corr0 = __expf(mrow[mt][0] - mn0), corr1 = __expf(mrow[mt][1] - mn1);
            mrow[mt][0] = mn0; mrow[mt][1] = mn1;

            float rs0 = 0.f, rs1 = 0.f;
#pragma unroll
            for (int nt = 0; nt < 8; nt++) {
                float p0 = __expf(sc[mt][nt][0] - mn0);
                float p1 = __expf(sc[mt][nt][1] - mn0);
                float p2 = __expf(sc[mt][nt][2] - mn1);
                float p3 = __expf(sc[mt][nt][3] - mn1);
                rs0 += p0 + p1; rs1 += p2 + p3;
                oc[mt][nt][0] *= corr0; oc[mt][nt][1] *= corr0;
                oc[mt][nt][2] *= corr1; oc[mt][nt][3] *= corr1;
                const int st = nt >> 1;
                if ((nt & 1) == 0) {
                    pp[mt][st][0] = h2_u32(__floats2half2_rn(p0, p1));
                    pp[mt][st][1] = h2_u32(__floats2half2_rn(p2, p3));
                } else {
                    pp[mt][st][2] = h2_u32(__floats2half2_rn(p0, p1));
                    pp[mt][st][3] = h2_u32(__floats2half2_rn(p2, p3));
                }
            }
            rs0 += __shfl_xor_sync(0xFFFFFFFFu, rs0, 1);
            rs0 += __shfl_xor_sync(0xFFFFFFFFu, rs0, 2);
            rs1 += __shfl_xor_sync(0xFFFFFFFFu, rs1, 1);
            rs1 += __shfl_xor_sync(0xFFFFFFFFu, rs1, 2);
            lrow[mt][0] = lrow[mt][0] * corr0 + rs0;
            lrow[mt][1] = lrow[mt][1] * corr1 + rs1;
        }

        // ---- O += P V (P in registers, V transposed in smem) ----
#pragma unroll
        for (int st = 0; st < 4; st++) {
            const int kk = st * 16;
#pragma unroll
            for (int nt = 0; nt < 8; nt++) {
                const int dcol = nt * 8 + g;
                uint32_t b0 = *reinterpret_cast<const uint32_t*>(&Vt[dcol * HPAD + kk + 2 * tig]);
                uint32_t b1 = *reinterpret_cast<const uint32_t*>(&Vt[dcol * HPAD + kk + 2 * tig + 8]);
                MMA_F16(oc[0][nt], pp[0][st], b0, b1);
                MMA_F16(oc[1][nt], pp[1][st], b0, b1);
            }
        }
    }

    // ---- finalize: fp16 store (feeds O-projection) ----
#pragma unroll
    for (int mt = 0; mt < 2; mt++) {
        const float inv0 = 1.0f / lrow[mt][0], inv1 = 1.0f / lrow[mt][1];
        const size_t gr0 = (size_t)(b * SEQ + q0 + wr + mt * 16 + g);
#pragma unroll
        for (int nt = 0; nt < 8; nt++) {
            const int col = h * HD + nt * 8 + tig * 2;
            *reinterpret_cast<__half2*>(O + gr0 * DM + col) =
                __floats2half2_rn(oc[mt][nt][0] * inv0, oc[mt][nt][1] * inv0);
            *reinterpret_cast<__half2*>(O + (gr0 + 8) * DM + col) =
                __floats2half2_rn(oc[mt][nt][2] * inv1, oc[mt][nt][3] * inv1);
        }
    }
}

// ---------------- launch ----------------------------------------------------
extern "C" void kernel_launch(void* const* d_in, const int* in_sizes, int n_in,
                              void* d_out, int out_size) {
    const float* x  = (const float*)d_in[0];
    const float* Wq = (const float*)d_in[1];
    const float* Wk = (const float*)d_in[2];
    const float* Wv = (const float*)d_in[3];
    const float* Wo = (const float*)d_in[4];
    float* out = (float*)d_out;

    float *gq, *gk, *gv;
    __half *oh, *xh, *wqh, *wkh, *wvh, *woh;
    cudaGetSymbolAddress((void**)&gq, g_q);
    cudaGetSymbolAddress((void**)&gk, g_k);
    cudaGetSymbolAddress((void**)&gv, g_v);
    cudaGetSymbolAddress((void**)&oh, g_oh);
    cudaGetSymbolAddress((void**)&xh, g_xh);
    cudaGetSymbolAddress((void**)&wqh, g_wqh);
    cudaGetSymbolAddress((void**)&wkh, g_wkh);
    cudaGetSymbolAddress((void**)&wvh, g_wvh);
    cudaGetSymbolAddress((void**)&woh, g_woh);

    static bool attr_set = false;
    if (!attr_set) {
        cudaFuncSetAttribute(gemm_qkv, cudaFuncAttributeMaxDynamicSharedMemorySize, GEMM_SMEM);
        cudaFuncSetAttribute(gemm_single, cudaFuncAttributeMaxDynamicSharedMemorySize, GEMM_SMEM);
        cudaFuncSetAttribute(attn_mma, cudaFuncAttributeMaxDynamicSharedMemorySize, ATTN_SMEM);
        attr_set = true;
    }

    // pre-round all GEMM operands to fp16 (one launch)
    cvt_all_kernel<<<1184, 256>>>(
        (const float4*)x,  (uint2*)xh,  (int)((size_t)NT * DM / 4),
        (const float4*)Wq, (uint2*)wqh, (int)((size_t)DM * DM / 4),
        (const float4*)Wk, (uint2*)wkh, (int)((size_t)(NKV * HD) * DM / 4),
        (const float4*)Wv, (uint2*)wvh, (int)((size_t)(NKV * HD) * DM / 4),
        (const float4*)Wo, (uint2*)woh, (int)((size_t)DM * DM / 4));

    // Q + K + V projections, one launch
    gemm_qkv<<<768, 256, GEMM_SMEM>>>(xh, wqh, gq, wkh, gk, wvh, gv);

    // RoPE on q and k, one launch
    int tq = NT * NH * 32;
    int tk = NT * NKV * 32;
    rope_all<<<(tq + tk + 255) / 256, 256>>>(gq, gk, tq, tq + tk);

    // causal GQA attention (fp16 mma flash, register-resident P)
    attn_mma<<<dim3(SEQ / 128, B_SZ * NH), 128, ATTN_SMEM>>>(gq, gk, gv, oh);

    // output projection into d_out
    gemm_single<<<dim3(DM / 128, NT / 128), 256, GEMM_SMEM>>>(oh, woh, out, DM, DM);
}